// round 11
// baseline (speedup 1.0000x reference)
#include <cuda_runtime.h>
#include <math.h>

// Geometry (fixed by the problem)
#define NPIX   401408        // 32*112*112
#define DIM    256
#define NCLS   4
#define NSUB   2
#define IMG    12544         // 112*112
#define NCHUNK (NPIX / 32)   // 12544

// d_out layout: nearest_img | proto_logits | proto_target | new_protos
#define OUT_LOGITS  (NPIX * NCLS)                 // 1605632
#define OUT_TARGET  (OUT_LOGITS + NPIX * 8)       // 4816896
#define OUT_PROTOS  (OUT_TARGET + NPIX)           // 5218304

#define FULLW 0xffffffffu

// ---------------- device scratch (no allocation allowed) ----------------
__device__ double        g_E[8];                 // Σ e_m per class   [c*2+m]
__device__ double        g_T2[8];                // iter-2 row sums
__device__ double        g_T3[8];                // iter-3 row sums
__device__ float         g_facc[8][DIM];         // masked feature sums [c*2+m][d]
__device__ int           g_cnt[8];               // assignment counts  [c*2+m]
__device__ float         g_protos[8][DIM];       // l2-normalized prototypes, row = k*2+m
__device__ float2        g_e[NPIX];              // (e0, e1) for the pixel's own class
__device__ unsigned char g_code[NPIX];           // bits 0-1: class, bit 2: correct
__device__ unsigned char g_ridx[NPIX];           // c*2+idx if correct else 255

__device__ __forceinline__ float wsum(float v) {
#pragma unroll
    for (int o = 16; o; o >>= 1) v += __shfl_xor_sync(FULLW, v, o);
    return v;
}

// value-folding reduction step: combines (a,b) across lane-pairs at `off`;
// result lands in a.
__device__ __forceinline__ void fold2(float& a, float b, int off, int lane) {
    bool hi = (lane & off) != 0;
    float keep = hi ? b : a;
    float send = hi ? a : b;
    a = keep + __shfl_xor_sync(FULLW, send, off);
}

// ---------------- K0: zero scratch + normalize prototypes ----------------
__global__ void k_init(const float* __restrict__ protos) {
    int tid = threadIdx.x;
    if (tid < 8)  { g_E[tid] = 0.0; g_T2[tid] = 0.0; g_T3[tid] = 0.0; g_cnt[tid] = 0; }
    for (int t = tid; t < 8 * DIM; t += blockDim.x) ((float*)g_facc)[t] = 0.f;

    int w = tid >> 5, lane = tid & 31;
    float p[8]; float ss = 0.f;
#pragma unroll
    for (int i = 0; i < 8; i++) { p[i] = protos[w * DIM + lane + 32 * i]; ss += p[i] * p[i]; }
    ss = wsum(ss);
    float inv = 1.0f / fmaxf(sqrtf(ss), 1e-12f);
#pragma unroll
    for (int i = 0; i < 8; i++) g_protos[w][lane + 32 * i] = p[i] * inv;
}

// ---------------- K1: main fused pass over out_feat (2 pixels interleaved) ----------------
__global__ void __launch_bounds__(256) k_main(
    const float* __restrict__ feat_in, const int* __restrict__ label,
    const float* __restrict__ fg, const float* __restrict__ fb,
    const float* __restrict__ mg, const float* __restrict__ mb,
    float* __restrict__ out)
{
    __shared__ float sprot[8][DIM];
    __shared__ float smg[4], smb[4];
    __shared__ float stage[4][32];
    __shared__ float sred[8];

    int tid = threadIdx.x;
    for (int t = tid; t < 8 * DIM; t += 256) ((float*)sprot)[t] = ((const float*)g_protos)[t];
    if (tid < 4) { smg[tid] = mg[tid]; smb[tid] = mb[tid]; }
    if (tid < 8) sred[tid] = 0.f;

    int w = tid >> 5, lane = tid & 31;

    const float4* fg4 = (const float4*)fg;
    const float4* fb4 = (const float4*)fb;
    float4 ga = fg4[lane], gb = fg4[lane + 32];
    float4 ba = fb4[lane], bb = fb4[lane + 32];
    float g[8]  = {ga.x, ga.y, ga.z, ga.w, gb.x, gb.y, gb.z, gb.w};
    float be[8] = {ba.x, ba.y, ba.z, ba.w, bb.x, bb.y, bb.z, bb.w};
    __syncthreads();

    // lane-0 accumulators for Σ e_m per class
    float f0 = 0.f, f1 = 0.f, f2 = 0.f, f3 = 0.f, f4 = 0.f, f5 = 0.f, f6 = 0.f, f7 = 0.f;

    float* logits = out + OUT_LOGITS;

    for (int chunk = blockIdx.x; chunk < NCHUNK; chunk += gridDim.x) {
#pragma unroll
        for (int h = 0; h < 2; h++) {
            int nb = chunk * 32 + w * 4 + 2 * h;
            // both pixel rows + labels in flight up front
            const float4* r0 = (const float4*)(feat_in + (size_t)nb * DIM);
            const float4* r1 = (const float4*)(feat_in + (size_t)(nb + 1) * DIM);
            float4 va0 = r0[lane], vb0 = r0[lane + 32];
            float4 va1 = r1[lane], vb1 = r1[lane + 32];
            int cls[2];
            cls[0] = label[nb]; cls[1] = label[nb + 1];

            float x[2][8];
            x[0][0]=va0.x; x[0][1]=va0.y; x[0][2]=va0.z; x[0][3]=va0.w;
            x[0][4]=vb0.x; x[0][5]=vb0.y; x[0][6]=vb0.z; x[0][7]=vb0.w;
            x[1][0]=va1.x; x[1][1]=va1.y; x[1][2]=va1.z; x[1][3]=va1.w;
            x[1][4]=vb1.x; x[1][5]=vb1.y; x[1][6]=vb1.z; x[1][7]=vb1.w;

            // LN (two independent fold chains; ptxas interleaves)
#pragma unroll
            for (int q = 0; q < 2; q++) {
                float s = 0.f, ss = 0.f;
#pragma unroll
                for (int i = 0; i < 8; i++) { s += x[q][i]; ss += x[q][i] * x[q][i]; }
                float v = (lane & 16) ? ss : s;
                float o = (lane & 16) ? s : ss;
                v += __shfl_xor_sync(FULLW, o, 16);
                v += __shfl_xor_sync(FULLW, v, 8);
                v += __shfl_xor_sync(FULLW, v, 4);
                v += __shfl_xor_sync(FULLW, v, 2);
                v += __shfl_xor_sync(FULLW, v, 1);
                s  = __shfl_sync(FULLW, v, lane & 15);
                ss = __shfl_sync(FULLW, v, (lane & 15) | 16);
                float mu = s * (1.f / DIM);
                float var = ss * (1.f / DIM) - mu * mu;
                float rstd = rsqrtf(var + 1e-5f);
                float nrm = 0.f;
#pragma unroll
                for (int i = 0; i < 8; i++) {
                    x[q][i] = (x[q][i] - mu) * rstd * g[i] + be[i];
                    nrm += x[q][i] * x[q][i];
                }
                nrm = wsum(nrm);
                float inv = 1.0f / fmaxf(sqrtf(nrm), 1e-12f);
#pragma unroll
                for (int i = 0; i < 8; i++) x[q][i] *= inv;
            }

            // dots: each proto float4 pair loaded ONCE, used for both pixels
            float d[2][8];
#pragma unroll
            for (int j = 0; j < 8; j++) {
                const float4* p4 = (const float4*)sprot[j];
                float4 pa = p4[lane], pb = p4[lane + 32];
#pragma unroll
                for (int q = 0; q < 2; q++) {
                    d[q][j] = x[q][0]*pa.x + x[q][1]*pa.y + x[q][2]*pa.z + x[q][3]*pa.w
                            + x[q][4]*pb.x + x[q][5]*pb.y + x[q][6]*pb.z + x[q][7]*pb.w;
                }
            }

            // folded 8-value reductions (independent chains per pixel)
#pragma unroll
            for (int q = 0; q < 2; q++) {
                fold2(d[q][0], d[q][4], 16, lane);
                fold2(d[q][1], d[q][5], 16, lane);
                fold2(d[q][2], d[q][6], 16, lane);
                fold2(d[q][3], d[q][7], 16, lane);
                fold2(d[q][0], d[q][2], 8, lane);
                fold2(d[q][1], d[q][3], 8, lane);
                fold2(d[q][0], d[q][1], 4, lane);
                d[q][0] += __shfl_xor_sync(FULLW, d[q][0], 2);
                d[q][0] += __shfl_xor_sync(FULLW, d[q][0], 1);
            }

            // permuted logits stores: lane 4j holds dot j = dot[k*2+m]
            if ((lane & 3) == 0) {
                int j = lane >> 2;
                int slot = ((j & 1) << 2) | (j >> 1);
                logits[(size_t)nb * 8 + slot]       = d[0][0];
                logits[(size_t)(nb + 1) * 8 + slot] = d[1][0];
            }

            // tails (gather + LN-of-4 + argmax + exp), per pixel
#pragma unroll
            for (int q = 0; q < 2; q++) {
                int n = nb + q;
                float dt0 = __shfl_sync(FULLW, d[q][0], 0);
                float dt1 = __shfl_sync(FULLW, d[q][0], 4);
                float dt2 = __shfl_sync(FULLW, d[q][0], 8);
                float dt3 = __shfl_sync(FULLW, d[q][0], 12);
                float dt4 = __shfl_sync(FULLW, d[q][0], 16);
                float dt5 = __shfl_sync(FULLW, d[q][0], 20);
                float dt6 = __shfl_sync(FULLW, d[q][0], 24);
                float dt7 = __shfl_sync(FULLW, d[q][0], 28);

                float nr0 = fmaxf(dt0, dt1), nr1 = fmaxf(dt2, dt3);
                float nr2 = fmaxf(dt4, dt5), nr3 = fmaxf(dt6, dt7);
                float m4 = 0.25f * (nr0 + nr1 + nr2 + nr3);
                float v4 = 0.25f * (nr0*nr0 + nr1*nr1 + nr2*nr2 + nr3*nr3) - m4 * m4;
                float r4 = rsqrtf(v4 + 1e-5f);
                float no0 = (nr0 - m4) * r4 * smg[0] + smb[0];
                float no1 = (nr1 - m4) * r4 * smg[1] + smb[1];
                float no2 = (nr2 - m4) * r4 * smg[2] + smb[2];
                float no3 = (nr3 - m4) * r4 * smg[3] + smb[3];
                int pred = 0; float best = no0;
                if (no1 > best) { best = no1; pred = 1; }
                if (no2 > best) { best = no2; pred = 2; }
                if (no3 > best) { best = no3; pred = 3; }
                int c = cls[q];
                float e0d = (c == 0) ? dt0 : (c == 1) ? dt2 : (c == 2) ? dt4 : dt6;
                float e1d = (c == 0) ? dt1 : (c == 1) ? dt3 : (c == 2) ? dt5 : dt7;
                float e0 = expf(e0d * 20.0f);   // /SK_EPS
                float e1 = expf(e1d * 20.0f);

                if (lane == 0) {
                    g_e[n] = make_float2(e0, e1);
                    g_code[n] = (unsigned char)(c | ((pred == c) << 2));
                    stage[0][w * 4 + 2 * h + q] = no0;
                    stage[1][w * 4 + 2 * h + q] = no1;
                    stage[2][w * 4 + 2 * h + q] = no2;
                    stage[3][w * 4 + 2 * h + q] = no3;
                    switch (c) {
                        case 0:  f0 += e0; f1 += e1; break;
                        case 1:  f2 += e0; f3 += e1; break;
                        case 2:  f4 += e0; f5 += e1; break;
                        default: f6 += e0; f7 += e1; break;
                    }
                }
            }
        }
        __syncthreads();
        // nearest_img[b,k,h,w]: 32-pixel chunks never cross b (32 | 12544)
        if (tid < 128) {
            int k = tid >> 5, i = tid & 31;
            int base = chunk * 32;
            int b = base / IMG;
            int off = base - b * IMG + i;
            out[(size_t)b * 4 * IMG + (size_t)k * IMG + off] = stage[k][i];
        }
        __syncthreads();
    }

    if (lane == 0) {
        atomicAdd(&sred[0], f0); atomicAdd(&sred[1], f1);
        atomicAdd(&sred[2], f2); atomicAdd(&sred[3], f3);
        atomicAdd(&sred[4], f4); atomicAdd(&sred[5], f5);
        atomicAdd(&sred[6], f6); atomicAdd(&sred[7], f7);
    }
    __syncthreads();
    if (tid < 8) atomicAdd(&g_E[tid], (double)sred[tid]);
}

// ---------------- K_R: sinkhorn row-sum reduction (stage 1 -> T2, stage 2 -> T3) ----------------
__global__ void __launch_bounds__(256) k_R(int stage) {
    __shared__ float sw[8];
    __shared__ float sred[8];
    int tid = threadIdx.x;
    if (tid < 8) {
        double src = (stage == 1) ? g_E[tid] : g_T2[tid];
        sw[tid] = (float)(1.0 / fmax(src, 1e-300));
        sred[tid] = 0.f;
    }
    __syncthreads();

    float f0 = 0.f, f1 = 0.f, f2 = 0.f, f3 = 0.f, f4 = 0.f, f5 = 0.f, f6 = 0.f, f7 = 0.f;

    int stride = gridDim.x * blockDim.x;
    for (int n = blockIdx.x * blockDim.x + tid; n < NPIX; n += stride) {
        int c = g_code[n] & 3;
        float2 e = g_e[n];
        float den = e.x * sw[2 * c] + e.y * sw[2 * c + 1];
        float ib = 1.0f / den;
        float v0 = e.x * ib, v1 = e.y * ib;
        switch (c) {
            case 0:  f0 += v0; f1 += v1; break;
            case 1:  f2 += v0; f3 += v1; break;
            case 2:  f4 += v0; f5 += v1; break;
            default: f6 += v0; f7 += v1; break;
        }
    }
    f0 = wsum(f0); f1 = wsum(f1); f2 = wsum(f2); f3 = wsum(f3);
    f4 = wsum(f4); f5 = wsum(f5); f6 = wsum(f6); f7 = wsum(f7);
    if ((tid & 31) == 0) {
        atomicAdd(&sred[0], f0); atomicAdd(&sred[1], f1);
        atomicAdd(&sred[2], f2); atomicAdd(&sred[3], f3);
        atomicAdd(&sred[4], f4); atomicAdd(&sred[5], f5);
        atomicAdd(&sred[6], f6); atomicAdd(&sred[7], f7);
    }
    __syncthreads();
    if (tid < 8) {
        double* dst = (stage == 1) ? g_T2 : g_T3;
        atomicAdd(&dst[tid], (double)sred[tid]);
    }
}

// ---------------- K_target: proto_target + final assignment byte ----------------
__global__ void k_target(float* __restrict__ target) {
    __shared__ float sw[8];
    int tid = threadIdx.x;
    if (tid < 8) sw[tid] = (float)(1.0 / fmax(g_T3[tid], 1e-300));
    __syncthreads();
    int n = blockIdx.x * blockDim.x + tid;
    if (n >= NPIX) return;
    unsigned char code = g_code[n];
    int c = code & 3;
    float2 e = g_e[n];
    int idx = (e.y * sw[2 * c + 1] > e.x * sw[2 * c]) ? 1 : 0;   // ties -> 0
    target[n] = (float)(idx + 2 * c);
    g_ridx[n] = (code & 4) ? (unsigned char)(c * 2 + idx) : (unsigned char)255;
}

// ---------------- K_accum: masked feature sums (only correct pixels) ----------------
__global__ void __launch_bounds__(256) k_accum(
    const float* __restrict__ feat_in,
    const float* __restrict__ fg, const float* __restrict__ fb)
{
    __shared__ float sfacc[8][DIM];
    __shared__ int   scnt[8];
    int tid = threadIdx.x;
    for (int t = tid; t < 8 * DIM; t += 256) ((float*)sfacc)[t] = 0.f;
    if (tid < 8) scnt[tid] = 0;

    int w = tid >> 5, lane = tid & 31;
    const float4* fg4 = (const float4*)fg;
    const float4* fb4 = (const float4*)fb;
    float4 ga = fg4[lane], gb = fg4[lane + 32];
    float4 ba = fb4[lane], bb = fb4[lane + 32];
    float g[8]  = {ga.x, ga.y, ga.z, ga.w, gb.x, gb.y, gb.z, gb.w};
    float be[8] = {ba.x, ba.y, ba.z, ba.w, bb.x, bb.y, bb.z, bb.w};
    __syncthreads();

    for (int chunk = blockIdx.x * 8 + w; chunk < NCHUNK; chunk += gridDim.x * 8) {
        int n0 = chunk * 32;
        int r = g_ridx[n0 + lane];
        unsigned mask = __ballot_sync(FULLW, r != 255);
        while (mask) {
            int j = __ffs(mask) - 1;
            mask &= mask - 1;
            int rr = __shfl_sync(FULLW, r, j);
            int n = n0 + j;

            const float4* row4 = (const float4*)(feat_in + (size_t)n * DIM);
            float4 va = row4[lane], vb = row4[lane + 32];
            float x[8] = {va.x, va.y, va.z, va.w, vb.x, vb.y, vb.z, vb.w};
            float s = 0.f, ss = 0.f;
#pragma unroll
            for (int i = 0; i < 8; i++) { s += x[i]; ss += x[i] * x[i]; }
            {
                float v = (lane & 16) ? ss : s;
                float o = (lane & 16) ? s : ss;
                v += __shfl_xor_sync(FULLW, o, 16);
                v += __shfl_xor_sync(FULLW, v, 8);
                v += __shfl_xor_sync(FULLW, v, 4);
                v += __shfl_xor_sync(FULLW, v, 2);
                v += __shfl_xor_sync(FULLW, v, 1);
                s  = __shfl_sync(FULLW, v, lane & 15);
                ss = __shfl_sync(FULLW, v, (lane & 15) | 16);
            }
            float mu = s * (1.f / DIM), var = ss * (1.f / DIM) - mu * mu;
            float rstd = rsqrtf(var + 1e-5f);
            float nrm = 0.f;
#pragma unroll
            for (int i = 0; i < 8; i++) {
                x[i] = (x[i] - mu) * rstd * g[i] + be[i];
                nrm += x[i] * x[i];
            }
            nrm = wsum(nrm);
            float inv = 1.f / fmaxf(sqrtf(nrm), 1e-12f);
#pragma unroll
            for (int i = 0; i < 4; i++) atomicAdd(&sfacc[rr][4 * lane + i], x[i] * inv);
#pragma unroll
            for (int i = 0; i < 4; i++) atomicAdd(&sfacc[rr][128 + 4 * lane + i], x[4 + i] * inv);
            if (lane == 0) atomicAdd(&scnt[rr], 1);
        }
    }
    __syncthreads();
    for (int t = tid; t < 8 * DIM; t += 256) atomicAdd(&((float*)g_facc)[t], ((float*)sfacc)[t]);
    if (tid < 8) atomicAdd(&g_cnt[tid], scnt[tid]);
}

// ---------------- K_final: EMA update + renormalize prototypes ----------------
__global__ void k_final(float* __restrict__ out) {
    int tid = threadIdx.x;
    int r = tid >> 5, lane = tid & 31;
    float f[8]; float ss = 0.f;
#pragma unroll
    for (int i = 0; i < 8; i++) { f[i] = g_facc[r][lane + 32 * i]; ss += f[i] * f[i]; }
    ss = wsum(ss);
    float inv = 1.f / fmaxf(sqrtf(ss), 1e-12f);
    int c = r >> 1;
    bool cond = ((g_cnt[c * 2] + g_cnt[c * 2 + 1]) > 0) && (g_cnt[r] != 0);
    float u[8]; float ss2 = 0.f;
#pragma unroll
    for (int i = 0; i < 8; i++) {
        float p = g_protos[r][lane + 32 * i];
        u[i] = cond ? (0.999f * p + 0.001f * (f[i] * inv)) : p;
        ss2 += u[i] * u[i];
    }
    ss2 = wsum(ss2);
    float inv2 = 1.f / fmaxf(sqrtf(ss2), 1e-12f);
    float* np = out + OUT_PROTOS;
#pragma unroll
    for (int i = 0; i < 8; i++) np[r * DIM + lane + 32 * i] = u[i] * inv2;
}

// ---------------- launch ----------------
extern "C" void kernel_launch(void* const* d_in, const int* in_sizes, int n_in,
                              void* d_out, int out_size)
{
    const float* feat   = (const float*)d_in[0];
    const int*   label  = (const int*)  d_in[1];
    const float* protos = (const float*)d_in[2];
    const float* fg     = (const float*)d_in[3];
    const float* fb     = (const float*)d_in[4];
    const float* mg     = (const float*)d_in[5];
    const float* mb     = (const float*)d_in[6];
    float* out = (float*)d_out;

    k_init<<<1, 256>>>(protos);
    k_main<<<1184, 256>>>(feat, label, fg, fb, mg, mb, out);
    k_R<<<1184, 256>>>(1);
    k_R<<<1184, 256>>>(2);
    k_target<<<NPIX / 256, 256>>>(out + OUT_TARGET);
    k_accum<<<1184, 256>>>(feat, fg, fb);
    k_final<<<1, 256>>>(out);
}

// round 12
// speedup vs baseline: 1.5452x; 1.5452x over previous
#include <cuda_runtime.h>
#include <math.h>

// Geometry (fixed by the problem)
#define NPIX   401408        // 32*112*112
#define DIM    256
#define NCLS   4
#define NSUB   2
#define IMG    12544         // 112*112
#define NCHUNK (NPIX / 32)   // 12544

// d_out layout: nearest_img | proto_logits | proto_target | new_protos
#define OUT_LOGITS  (NPIX * NCLS)                 // 1605632
#define OUT_TARGET  (OUT_LOGITS + NPIX * 8)       // 4816896
#define OUT_PROTOS  (OUT_TARGET + NPIX)           // 5218304

#define FULLW 0xffffffffu

// ---------------- device scratch (no allocation allowed) ----------------
__device__ double        g_E[8];                 // Σ e_m per class   [c*2+m]
__device__ double        g_T2[8];                // iter-2 row sums
__device__ double        g_T3[8];                // iter-3 row sums
__device__ float         g_facc[8][DIM];         // masked feature sums [c*2+m][d]
__device__ int           g_cnt[8];               // assignment counts  [c*2+m]
__device__ float         g_protos[8][DIM];       // l2-normalized prototypes, row = k*2+m
__device__ float2        g_e[NPIX];              // (e0, e1) for the pixel's own class
__device__ unsigned char g_code[NPIX];           // bits 0-1: class, bit 2: correct
__device__ unsigned char g_ridx[NPIX];           // c*2+idx if correct else 255

__device__ __forceinline__ float wsum(float v) {
#pragma unroll
    for (int o = 16; o; o >>= 1) v += __shfl_xor_sync(FULLW, v, o);
    return v;
}

// value-folding reduction step
__device__ __forceinline__ void fold2(float& a, float b, int off, int lane) {
    bool hi = (lane & off) != 0;
    float keep = hi ? b : a;
    float send = hi ? a : b;
    a = keep + __shfl_xor_sync(FULLW, send, off);
}

// ---------------- K0: zero scratch + normalize prototypes ----------------
__global__ void k_init(const float* __restrict__ protos) {
    int tid = threadIdx.x;
    if (tid < 8)  { g_E[tid] = 0.0; g_T2[tid] = 0.0; g_T3[tid] = 0.0; g_cnt[tid] = 0; }
    for (int t = tid; t < 8 * DIM; t += blockDim.x) ((float*)g_facc)[t] = 0.f;

    int w = tid >> 5, lane = tid & 31;
    float p[8]; float ss = 0.f;
#pragma unroll
    for (int i = 0; i < 8; i++) { p[i] = protos[w * DIM + lane + 32 * i]; ss += p[i] * p[i]; }
    ss = wsum(ss);
    float inv = 1.0f / fmaxf(sqrtf(ss), 1e-12f);
#pragma unroll
    for (int i = 0; i < 8; i++) g_protos[w][lane + 32 * i] = p[i] * inv;
}

// ---------------- K1: main fused pass over out_feat (round-10 shape, slimmed) ----------------
__global__ void __launch_bounds__(256) k_main(
    const float* __restrict__ feat_in, const int* __restrict__ label,
    const float* __restrict__ fg, const float* __restrict__ fb,
    const float* __restrict__ mg, const float* __restrict__ mb,
    float* __restrict__ out)
{
    __shared__ float sprot[8][DIM];
    __shared__ float smg[4], smb[4];
    __shared__ float stage[4][32];

    int tid = threadIdx.x;
    for (int t = tid; t < 8 * DIM; t += 256) ((float*)sprot)[t] = ((const float*)g_protos)[t];
    if (tid < 4) { smg[tid] = mg[tid]; smb[tid] = mb[tid]; }

    int w = tid >> 5, lane = tid & 31;

    const float4* fg4 = (const float4*)fg;
    const float4* fb4 = (const float4*)fb;
    float4 ga = fg4[lane], gb = fg4[lane + 32];
    float4 ba = fb4[lane], bb = fb4[lane + 32];
    float g[8]  = {ga.x, ga.y, ga.z, ga.w, gb.x, gb.y, gb.z, gb.w};
    float be[8] = {ba.x, ba.y, ba.z, ba.w, bb.x, bb.y, bb.z, bb.w};
    __syncthreads();

    float* logits = out + OUT_LOGITS;

    for (int chunk = blockIdx.x; chunk < NCHUNK; chunk += gridDim.x) {
#pragma unroll 1
        for (int p = 0; p < 4; p++) {
            int n = chunk * 32 + w * 4 + p;
            const float4* row4 = (const float4*)(feat_in + (size_t)n * DIM);
            float4 va = row4[lane], vb = row4[lane + 32];
            float x[8] = {va.x, va.y, va.z, va.w, vb.x, vb.y, vb.z, vb.w};
            float s = 0.f, ss = 0.f;
#pragma unroll
            for (int i = 0; i < 8; i++) { s += x[i]; ss += x[i] * x[i]; }
            // folded (s,ss) reduction: 7 shuffles
            {
                float v = (lane & 16) ? ss : s;
                float o = (lane & 16) ? s : ss;
                v += __shfl_xor_sync(FULLW, o, 16);
                v += __shfl_xor_sync(FULLW, v, 8);
                v += __shfl_xor_sync(FULLW, v, 4);
                v += __shfl_xor_sync(FULLW, v, 2);
                v += __shfl_xor_sync(FULLW, v, 1);
                s  = __shfl_sync(FULLW, v, lane & 15);
                ss = __shfl_sync(FULLW, v, (lane & 15) | 16);
            }
            float mu = s * (1.f / DIM);
            float var = ss * (1.f / DIM) - mu * mu;
            float rstd = rsqrtf(var + 1e-5f);
            float nrm = 0.f;
#pragma unroll
            for (int i = 0; i < 8; i++) {
                x[i] = (x[i] - mu) * rstd * g[i] + be[i];
                nrm += x[i] * x[i];
            }
            nrm = wsum(nrm);
            float inv = 1.0f / fmaxf(sqrtf(nrm), 1e-12f);
#pragma unroll
            for (int i = 0; i < 8; i++) x[i] *= inv;

            // per-lane partial dots
            float d0, d1, d2, d3, d4, d5, d6, d7;
            {
                float dd[8];
#pragma unroll
                for (int j = 0; j < 8; j++) {
                    const float4* p4 = (const float4*)sprot[j];
                    float4 pa = p4[lane], pb = p4[lane + 32];
                    dd[j] = x[0]*pa.x + x[1]*pa.y + x[2]*pa.z + x[3]*pa.w
                          + x[4]*pb.x + x[5]*pb.y + x[6]*pb.z + x[7]*pb.w;
                }
                d0 = dd[0]; d1 = dd[1]; d2 = dd[2]; d3 = dd[3];
                d4 = dd[4]; d5 = dd[5]; d6 = dd[6]; d7 = dd[7];
            }
            // folded 8-value reduction: lane 4j ends with full dot[j]
            fold2(d0, d4, 16, lane);
            fold2(d1, d5, 16, lane);
            fold2(d2, d6, 16, lane);
            fold2(d3, d7, 16, lane);
            fold2(d0, d2, 8, lane);
            fold2(d1, d3, 8, lane);
            fold2(d0, d1, 4, lane);
            d0 += __shfl_xor_sync(FULLW, d0, 2);
            d0 += __shfl_xor_sync(FULLW, d0, 1);

            // direct permuted logits store: lane 4j holds dot j = dot[k*2+m]
            if ((lane & 3) == 0) {
                int j = lane >> 2;
                int slot = ((j & 1) << 2) | (j >> 1);
                logits[(size_t)n * 8 + slot] = d0;
            }

            // gather all 8 dots to every lane
            float dt0 = __shfl_sync(FULLW, d0, 0);
            float dt1 = __shfl_sync(FULLW, d0, 4);
            float dt2 = __shfl_sync(FULLW, d0, 8);
            float dt3 = __shfl_sync(FULLW, d0, 12);
            float dt4 = __shfl_sync(FULLW, d0, 16);
            float dt5 = __shfl_sync(FULLW, d0, 20);
            float dt6 = __shfl_sync(FULLW, d0, 24);
            float dt7 = __shfl_sync(FULLW, d0, 28);

            // tail on ALL lanes (divergence-free)
            float nr0 = fmaxf(dt0, dt1), nr1 = fmaxf(dt2, dt3);
            float nr2 = fmaxf(dt4, dt5), nr3 = fmaxf(dt6, dt7);
            float m4 = 0.25f * (nr0 + nr1 + nr2 + nr3);
            float v4 = 0.25f * (nr0*nr0 + nr1*nr1 + nr2*nr2 + nr3*nr3) - m4 * m4;
            float r4 = rsqrtf(v4 + 1e-5f);
            float no0 = (nr0 - m4) * r4 * smg[0] + smb[0];
            float no1 = (nr1 - m4) * r4 * smg[1] + smb[1];
            float no2 = (nr2 - m4) * r4 * smg[2] + smb[2];
            float no3 = (nr3 - m4) * r4 * smg[3] + smb[3];
            int pred = 0; float best = no0;
            if (no1 > best) { best = no1; pred = 1; }
            if (no2 > best) { best = no2; pred = 2; }
            if (no3 > best) { best = no3; pred = 3; }
            int c = label[n];
            float e0d = (c == 0) ? dt0 : (c == 1) ? dt2 : (c == 2) ? dt4 : dt6;
            float e1d = (c == 0) ? dt1 : (c == 1) ? dt3 : (c == 2) ? dt5 : dt7;
            float e0 = expf(e0d * 20.0f);   // /SK_EPS
            float e1 = expf(e1d * 20.0f);

            if (lane == 0) {
                g_e[n] = make_float2(e0, e1);
                g_code[n] = (unsigned char)(c | ((pred == c) << 2));
                stage[0][w * 4 + p] = no0;
                stage[1][w * 4 + p] = no1;
                stage[2][w * 4 + p] = no2;
                stage[3][w * 4 + p] = no3;
            }
        }
        __syncthreads();
        // nearest_img[b,k,h,w]: 32-pixel chunks never cross b (32 | 12544)
        if (tid < 128) {
            int k = tid >> 5, i = tid & 31;
            int base = chunk * 32;
            int b = base / IMG;
            int off = base - b * IMG + i;
            out[(size_t)b * 4 * IMG + (size_t)k * IMG + off] = stage[k][i];
        }
        __syncthreads();
    }
}

// ---------------- K_R: sinkhorn reductions (stage 0 -> E, 1 -> T2, 2 -> T3) ----------------
__global__ void __launch_bounds__(256) k_R(int stage) {
    __shared__ float sw[8];
    __shared__ float sred[8];
    int tid = threadIdx.x;
    if (tid < 8) {
        double src = (stage == 1) ? g_E[tid] : g_T2[tid];
        sw[tid] = (float)(1.0 / fmax(src, 1e-300));
        sred[tid] = 0.f;
    }
    __syncthreads();

    float f0 = 0.f, f1 = 0.f, f2 = 0.f, f3 = 0.f, f4 = 0.f, f5 = 0.f, f6 = 0.f, f7 = 0.f;

    int stride = gridDim.x * blockDim.x;
    for (int n = blockIdx.x * blockDim.x + tid; n < NPIX; n += stride) {
        int c = g_code[n] & 3;
        float2 e = g_e[n];
        float v0, v1;
        if (stage == 0) {
            v0 = e.x; v1 = e.y;
        } else {
            float den = e.x * sw[2 * c] + e.y * sw[2 * c + 1];
            float ib = 1.0f / den;
            v0 = e.x * ib; v1 = e.y * ib;
        }
        switch (c) {
            case 0:  f0 += v0; f1 += v1; break;
            case 1:  f2 += v0; f3 += v1; break;
            case 2:  f4 += v0; f5 += v1; break;
            default: f6 += v0; f7 += v1; break;
        }
    }
    f0 = wsum(f0); f1 = wsum(f1); f2 = wsum(f2); f3 = wsum(f3);
    f4 = wsum(f4); f5 = wsum(f5); f6 = wsum(f6); f7 = wsum(f7);
    if ((tid & 31) == 0) {
        atomicAdd(&sred[0], f0); atomicAdd(&sred[1], f1);
        atomicAdd(&sred[2], f2); atomicAdd(&sred[3], f3);
        atomicAdd(&sred[4], f4); atomicAdd(&sred[5], f5);
        atomicAdd(&sred[6], f6); atomicAdd(&sred[7], f7);
    }
    __syncthreads();
    if (tid < 8) {
        double* dst = (stage == 0) ? g_E : (stage == 1) ? g_T2 : g_T3;
        atomicAdd(&dst[tid], (double)sred[tid]);
    }
}

// ---------------- K_target: proto_target + final assignment byte ----------------
__global__ void k_target(float* __restrict__ target) {
    __shared__ float sw[8];
    int tid = threadIdx.x;
    if (tid < 8) sw[tid] = (float)(1.0 / fmax(g_T3[tid], 1e-300));
    __syncthreads();
    int n = blockIdx.x * blockDim.x + tid;
    if (n >= NPIX) return;
    unsigned char code = g_code[n];
    int c = code & 3;
    float2 e = g_e[n];
    int idx = (e.y * sw[2 * c + 1] > e.x * sw[2 * c]) ? 1 : 0;   // ties -> 0
    target[n] = (float)(idx + 2 * c);
    g_ridx[n] = (code & 4) ? (unsigned char)(c * 2 + idx) : (unsigned char)255;
}

// ---------------- K_accum: masked feature sums, bucket-outermost, atomic-free rows ----------------
__global__ void __launch_bounds__(256) k_accum(
    const float* __restrict__ feat_in,
    const float* __restrict__ fg, const float* __restrict__ fb)
{
    __shared__ float sfacc[8][DIM];
    __shared__ int   scnt[8];
    int tid = threadIdx.x;
    for (int t = tid; t < 8 * DIM; t += 256) ((float*)sfacc)[t] = 0.f;
    if (tid < 8) scnt[tid] = 0;

    int w = tid >> 5, lane = tid & 31;
    const float4* fg4 = (const float4*)fg;
    const float4* fb4 = (const float4*)fb;
    float4 ga = fg4[lane], gb = fg4[lane + 32];
    float4 ba = fb4[lane], bb = fb4[lane + 32];
    float g[8]  = {ga.x, ga.y, ga.z, ga.w, gb.x, gb.y, gb.z, gb.w};
    float be[8] = {ba.x, ba.y, ba.z, ba.w, bb.x, bb.y, bb.z, bb.w};
    __syncthreads();

#pragma unroll 1
    for (int r = 0; r < 8; r++) {
        float acc[8] = {0.f, 0.f, 0.f, 0.f, 0.f, 0.f, 0.f, 0.f};
        int cnt = 0;
        for (int chunk = blockIdx.x * 8 + w; chunk < NCHUNK; chunk += gridDim.x * 8) {
            int n0 = chunk * 32;
            int rl = g_ridx[n0 + lane];
            unsigned mask = __ballot_sync(FULLW, rl == r);
            while (mask) {
                int j = __ffs(mask) - 1;
                mask &= mask - 1;
                int n = n0 + j;

                const float4* row4 = (const float4*)(feat_in + (size_t)n * DIM);
                float4 va = row4[lane], vb = row4[lane + 32];
                float x[8] = {va.x, va.y, va.z, va.w, vb.x, vb.y, vb.z, vb.w};
                float s = 0.f, ss = 0.f;
#pragma unroll
                for (int i = 0; i < 8; i++) { s += x[i]; ss += x[i] * x[i]; }
                {
                    float v = (lane & 16) ? ss : s;
                    float o = (lane & 16) ? s : ss;
                    v += __shfl_xor_sync(FULLW, o, 16);
                    v += __shfl_xor_sync(FULLW, v, 8);
                    v += __shfl_xor_sync(FULLW, v, 4);
                    v += __shfl_xor_sync(FULLW, v, 2);
                    v += __shfl_xor_sync(FULLW, v, 1);
                    s  = __shfl_sync(FULLW, v, lane & 15);
                    ss = __shfl_sync(FULLW, v, (lane & 15) | 16);
                }
                float mu = s * (1.f / DIM), var = ss * (1.f / DIM) - mu * mu;
                float rstd = rsqrtf(var + 1e-5f);
                float nrm = 0.f;
#pragma unroll
                for (int i = 0; i < 8; i++) {
                    x[i] = (x[i] - mu) * rstd * g[i] + be[i];
                    nrm += x[i] * x[i];
                }
                nrm = wsum(nrm);
                float inv = 1.f / fmaxf(sqrtf(nrm), 1e-12f);
#pragma unroll
                for (int i = 0; i < 8; i++) acc[i] += x[i] * inv;
                cnt++;
            }
        }
        // flush bucket r (8 smem atomics/lane per bucket, conflict-free in-warp)
#pragma unroll
        for (int i = 0; i < 4; i++) atomicAdd(&sfacc[r][4 * lane + i], acc[i]);
#pragma unroll
        for (int i = 0; i < 4; i++) atomicAdd(&sfacc[r][128 + 4 * lane + i], acc[4 + i]);
        if (lane == 0) atomicAdd(&scnt[r], cnt);
    }
    __syncthreads();
    for (int t = tid; t < 8 * DIM; t += 256) atomicAdd(&((float*)g_facc)[t], ((float*)sfacc)[t]);
    if (tid < 8) atomicAdd(&g_cnt[tid], scnt[tid]);
}

// ---------------- K_final: EMA update + renormalize prototypes ----------------
__global__ void k_final(float* __restrict__ out) {
    int tid = threadIdx.x;
    int r = tid >> 5, lane = tid & 31;
    float f[8]; float ss = 0.f;
#pragma unroll
    for (int i = 0; i < 8; i++) { f[i] = g_facc[r][lane + 32 * i]; ss += f[i] * f[i]; }
    ss = wsum(ss);
    float inv = 1.f / fmaxf(sqrtf(ss), 1e-12f);
    int c = r >> 1;
    bool cond = ((g_cnt[c * 2] + g_cnt[c * 2 + 1]) > 0) && (g_cnt[r] != 0);
    float u[8]; float ss2 = 0.f;
#pragma unroll
    for (int i = 0; i < 8; i++) {
        float p = g_protos[r][lane + 32 * i];
        u[i] = cond ? (0.999f * p + 0.001f * (f[i] * inv)) : p;
        ss2 += u[i] * u[i];
    }
    ss2 = wsum(ss2);
    float inv2 = 1.f / fmaxf(sqrtf(ss2), 1e-12f);
    float* np = out + OUT_PROTOS;
#pragma unroll
    for (int i = 0; i < 8; i++) np[r * DIM + lane + 32 * i] = u[i] * inv2;
}

// ---------------- launch ----------------
extern "C" void kernel_launch(void* const* d_in, const int* in_sizes, int n_in,
                              void* d_out, int out_size)
{
    const float* feat   = (const float*)d_in[0];
    const int*   label  = (const int*)  d_in[1];
    const float* protos = (const float*)d_in[2];
    const float* fg     = (const float*)d_in[3];
    const float* fb     = (const float*)d_in[4];
    const float* mg     = (const float*)d_in[5];
    const float* mb     = (const float*)d_in[6];
    float* out = (float*)d_out;

    k_init<<<1, 256>>>(protos);
    k_main<<<1184, 256>>>(feat, label, fg, fb, mg, mb, out);
    k_R<<<1184, 256>>>(0);   // Σe  -> g_E
    k_R<<<1184, 256>>>(1);   //     -> g_T2
    k_R<<<1184, 256>>>(2);   //     -> g_T3
    k_target<<<NPIX / 256, 256>>>(out + OUT_TARGET);
    k_accum<<<1184, 256>>>(feat, fg, fb);
    k_final<<<1, 256>>>(out);
}

// round 13
// speedup vs baseline: 1.6665x; 1.0785x over previous
#include <cuda_runtime.h>
#include <math.h>

// Geometry (fixed by the problem)
#define NPIX   401408        // 32*112*112
#define DIM    256
#define NCLS   4
#define NSUB   2
#define IMG    12544         // 112*112
#define NCHUNK (NPIX / 32)   // 12544

// d_out layout: nearest_img | proto_logits | proto_target | new_protos
#define OUT_LOGITS  (NPIX * NCLS)                 // 1605632
#define OUT_TARGET  (OUT_LOGITS + NPIX * 8)       // 4816896
#define OUT_PROTOS  (OUT_TARGET + NPIX)           // 5218304

#define FULLW 0xffffffffu

typedef unsigned long long u64;

// ---------------- packed f32x2 helpers (Blackwell FFMA2 pipe) ----------------
__device__ __forceinline__ u64 f2_mul(u64 a, u64 b) {
    u64 r; asm("mul.rn.f32x2 %0, %1, %2;" : "=l"(r) : "l"(a), "l"(b)); return r;
}
__device__ __forceinline__ u64 f2_add(u64 a, u64 b) {
    u64 r; asm("add.rn.f32x2 %0, %1, %2;" : "=l"(r) : "l"(a), "l"(b)); return r;
}
__device__ __forceinline__ u64 f2_fma(u64 a, u64 b, u64 c) {
    u64 r; asm("fma.rn.f32x2 %0, %1, %2, %3;" : "=l"(r) : "l"(a), "l"(b), "l"(c)); return r;
}
__device__ __forceinline__ float f2_hadd(u64 a) {
    float lo, hi; asm("mov.b64 {%0, %1}, %2;" : "=f"(lo), "=f"(hi) : "l"(a)); return lo + hi;
}
__device__ __forceinline__ void f2_unpack(u64 a, float& lo, float& hi) {
    asm("mov.b64 {%0, %1}, %2;" : "=f"(lo), "=f"(hi) : "l"(a));
}
__device__ __forceinline__ u64 f2_bcast(float v) {
    u64 r; asm("mov.b64 %0, {%1, %1};" : "=l"(r) : "f"(v)); return r;
}

// ---------------- device scratch (no allocation allowed) ----------------
__device__ double        g_E[8];                 // Σ e_m per class   [c*2+m]
__device__ double        g_T2[8];                // iter-2 row sums
__device__ double        g_T3[8];                // iter-3 row sums
__device__ float         g_facc[8][DIM];         // masked feature sums [c*2+m][d]
__device__ int           g_cnt[8];               // assignment counts  [c*2+m]
__device__ float         g_protos[8][DIM];       // l2-normalized prototypes, row = k*2+m
__device__ float2        g_e[NPIX];              // (e0, e1) for the pixel's own class
__device__ unsigned char g_code[NPIX];           // bits 0-1: class, bit 2: correct
__device__ unsigned char g_ridx[NPIX];           // c*2+idx if correct else 255

__device__ __forceinline__ float wsum(float v) {
#pragma unroll
    for (int o = 16; o; o >>= 1) v += __shfl_xor_sync(FULLW, v, o);
    return v;
}

// value-folding reduction step
__device__ __forceinline__ void fold2(float& a, float b, int off, int lane) {
    bool hi = (lane & off) != 0;
    float keep = hi ? b : a;
    float send = hi ? a : b;
    a = keep + __shfl_xor_sync(FULLW, send, off);
}

// ---------------- K0: zero scratch + normalize prototypes ----------------
__global__ void k_init(const float* __restrict__ protos) {
    int tid = threadIdx.x;
    if (tid < 8)  { g_E[tid] = 0.0; g_T2[tid] = 0.0; g_T3[tid] = 0.0; g_cnt[tid] = 0; }
    for (int t = tid; t < 8 * DIM; t += blockDim.x) ((float*)g_facc)[t] = 0.f;

    int w = tid >> 5, lane = tid & 31;
    float p[8]; float ss = 0.f;
#pragma unroll
    for (int i = 0; i < 8; i++) { p[i] = protos[w * DIM + lane + 32 * i]; ss += p[i] * p[i]; }
    ss = wsum(ss);
    float inv = 1.0f / fmaxf(sqrtf(ss), 1e-12f);
#pragma unroll
    for (int i = 0; i < 8; i++) g_protos[w][lane + 32 * i] = p[i] * inv;
}

// ---------------- K1: main fused pass over out_feat (packed f32x2) ----------------
__global__ void __launch_bounds__(256) k_main(
    const float* __restrict__ feat_in, const int* __restrict__ label,
    const float* __restrict__ fg, const float* __restrict__ fb,
    const float* __restrict__ mg, const float* __restrict__ mb,
    float* __restrict__ out)
{
    __shared__ float sprot[8][DIM];
    __shared__ float smg[4], smb[4];
    __shared__ float stage[4][32];

    int tid = threadIdx.x;
    for (int t = tid; t < 8 * DIM; t += 256) ((float*)sprot)[t] = ((const float*)g_protos)[t];
    if (tid < 4) { smg[tid] = mg[tid]; smb[tid] = mb[tid]; }

    int w = tid >> 5, lane = tid & 31;

    // packed per-lane gamma/beta (elements 4*lane.., 128+4*lane..)
    const ulonglong2* fgp = (const ulonglong2*)fg;
    const ulonglong2* fbp = (const ulonglong2*)fb;
    ulonglong2 gA = fgp[lane], gB = fgp[lane + 32];
    ulonglong2 bA = fbp[lane], bB = fbp[lane + 32];
    u64 g2[4]  = {gA.x, gA.y, gB.x, gB.y};
    u64 be2[4] = {bA.x, bA.y, bB.x, bB.y};
    __syncthreads();

    float* logits = out + OUT_LOGITS;

    for (int chunk = blockIdx.x; chunk < NCHUNK; chunk += gridDim.x) {
#pragma unroll 1
        for (int p = 0; p < 4; p++) {
            int n = chunk * 32 + w * 4 + p;
            const ulonglong2* row = (const ulonglong2*)(feat_in + (size_t)n * DIM);
            ulonglong2 ra = row[lane], rb = row[lane + 32];
            u64 x2[4] = {ra.x, ra.y, rb.x, rb.y};

            // packed sums
            u64 s2 = f2_add(f2_add(x2[0], x2[1]), f2_add(x2[2], x2[3]));
            u64 q2 = f2_mul(x2[0], x2[0]);
            q2 = f2_fma(x2[1], x2[1], q2);
            q2 = f2_fma(x2[2], x2[2], q2);
            q2 = f2_fma(x2[3], x2[3], q2);
            float s = f2_hadd(s2), ss = f2_hadd(q2);
            // folded (s,ss) reduction: 7 shuffles
            {
                float v = (lane & 16) ? ss : s;
                float o = (lane & 16) ? s : ss;
                v += __shfl_xor_sync(FULLW, o, 16);
                v += __shfl_xor_sync(FULLW, v, 8);
                v += __shfl_xor_sync(FULLW, v, 4);
                v += __shfl_xor_sync(FULLW, v, 2);
                v += __shfl_xor_sync(FULLW, v, 1);
                s  = __shfl_sync(FULLW, v, lane & 15);
                ss = __shfl_sync(FULLW, v, (lane & 15) | 16);
            }
            float mu = s * (1.f / DIM);
            float var = ss * (1.f / DIM) - mu * mu;
            float rstd = rsqrtf(var + 1e-5f);

            // LN transform (packed): y = (x*rstd - mu*rstd)*g + be
            u64 A2 = f2_bcast(rstd), M2 = f2_bcast(-mu * rstd);
            u64 y2[4];
#pragma unroll
            for (int i = 0; i < 4; i++) {
                u64 t = f2_fma(x2[i], A2, M2);
                y2[i] = f2_fma(t, g2[i], be2[i]);
            }
            // raw norm (reduced in parallel with dot folds; inv applied post-reduction)
            u64 n2 = f2_mul(y2[0], y2[0]);
            n2 = f2_fma(y2[1], y2[1], n2);
            n2 = f2_fma(y2[2], y2[2], n2);
            n2 = f2_fma(y2[3], y2[3], n2);
            float nrm = f2_hadd(n2);

            // raw dots (packed)
            float d0, d1, d2, d3, d4, d5, d6, d7;
            {
                float dd[8];
#pragma unroll
                for (int j = 0; j < 8; j++) {
                    const ulonglong2* p4 = (const ulonglong2*)sprot[j];
                    ulonglong2 pa = p4[lane], pb = p4[lane + 32];
                    u64 a2 = f2_mul(y2[0], pa.x);
                    a2 = f2_fma(y2[1], pa.y, a2);
                    a2 = f2_fma(y2[2], pb.x, a2);
                    a2 = f2_fma(y2[3], pb.y, a2);
                    dd[j] = f2_hadd(a2);
                }
                d0 = dd[0]; d1 = dd[1]; d2 = dd[2]; d3 = dd[3];
                d4 = dd[4]; d5 = dd[5]; d6 = dd[6]; d7 = dd[7];
            }
            nrm = wsum(nrm);                         // independent chain -> ILP
            float inv = 1.0f / fmaxf(sqrtf(nrm), 1e-12f);

            // folded 8-value reduction: lane 4j ends with full raw dot[j]
            fold2(d0, d4, 16, lane);
            fold2(d1, d5, 16, lane);
            fold2(d2, d6, 16, lane);
            fold2(d3, d7, 16, lane);
            fold2(d0, d2, 8, lane);
            fold2(d1, d3, 8, lane);
            fold2(d0, d1, 4, lane);
            d0 += __shfl_xor_sync(FULLW, d0, 2);
            d0 += __shfl_xor_sync(FULLW, d0, 1);
            d0 *= inv;                               // l2-normalization applied once

            // direct permuted logits store: lane 4j holds dot j = dot[k*2+m]
            if ((lane & 3) == 0) {
                int j = lane >> 2;
                int slot = ((j & 1) << 2) | (j >> 1);
                logits[(size_t)n * 8 + slot] = d0;
            }

            // gather all 8 dots to every lane
            float dt0 = __shfl_sync(FULLW, d0, 0);
            float dt1 = __shfl_sync(FULLW, d0, 4);
            float dt2 = __shfl_sync(FULLW, d0, 8);
            float dt3 = __shfl_sync(FULLW, d0, 12);
            float dt4 = __shfl_sync(FULLW, d0, 16);
            float dt5 = __shfl_sync(FULLW, d0, 20);
            float dt6 = __shfl_sync(FULLW, d0, 24);
            float dt7 = __shfl_sync(FULLW, d0, 28);

            // tail on ALL lanes (divergence-free)
            float nr0 = fmaxf(dt0, dt1), nr1 = fmaxf(dt2, dt3);
            float nr2 = fmaxf(dt4, dt5), nr3 = fmaxf(dt6, dt7);
            float m4 = 0.25f * (nr0 + nr1 + nr2 + nr3);
            float v4 = 0.25f * (nr0*nr0 + nr1*nr1 + nr2*nr2 + nr3*nr3) - m4 * m4;
            float r4 = rsqrtf(v4 + 1e-5f);
            float no0 = (nr0 - m4) * r4 * smg[0] + smb[0];
            float no1 = (nr1 - m4) * r4 * smg[1] + smb[1];
            float no2 = (nr2 - m4) * r4 * smg[2] + smb[2];
            float no3 = (nr3 - m4) * r4 * smg[3] + smb[3];
            int pred = 0; float best = no0;
            if (no1 > best) { best = no1; pred = 1; }
            if (no2 > best) { best = no2; pred = 2; }
            if (no3 > best) { best = no3; pred = 3; }
            int c = label[n];
            float e0d = (c == 0) ? dt0 : (c == 1) ? dt2 : (c == 2) ? dt4 : dt6;
            float e1d = (c == 0) ? dt1 : (c == 1) ? dt3 : (c == 2) ? dt5 : dt7;
            float e0 = expf(e0d * 20.0f);   // /SK_EPS
            float e1 = expf(e1d * 20.0f);

            if (lane == 0) {
                g_e[n] = make_float2(e0, e1);
                g_code[n] = (unsigned char)(c | ((pred == c) << 2));
                stage[0][w * 4 + p] = no0;
                stage[1][w * 4 + p] = no1;
                stage[2][w * 4 + p] = no2;
                stage[3][w * 4 + p] = no3;
            }
        }
        __syncthreads();
        // nearest_img[b,k,h,w]: 32-pixel chunks never cross b (32 | 12544)
        if (tid < 128) {
            int k = tid >> 5, i = tid & 31;
            int base = chunk * 32;
            int b = base / IMG;
            int off = base - b * IMG + i;
            out[(size_t)b * 4 * IMG + (size_t)k * IMG + off] = stage[k][i];
        }
        __syncthreads();
    }
}

// ---------------- K_R: sinkhorn reductions (stage 0 -> E, 1 -> T2, 2 -> T3) ----------------
__global__ void __launch_bounds__(256) k_R(int stage) {
    __shared__ float sw[8];
    __shared__ float sred[8];
    int tid = threadIdx.x;
    if (tid < 8) {
        double src = (stage == 1) ? g_E[tid] : g_T2[tid];
        sw[tid] = (float)(1.0 / fmax(src, 1e-300));
        sred[tid] = 0.f;
    }
    __syncthreads();

    float f0 = 0.f, f1 = 0.f, f2 = 0.f, f3 = 0.f, f4 = 0.f, f5 = 0.f, f6 = 0.f, f7 = 0.f;

    int stride = gridDim.x * blockDim.x;
    for (int n = blockIdx.x * blockDim.x + tid; n < NPIX; n += stride) {
        int c = g_code[n] & 3;
        float2 e = g_e[n];
        float v0, v1;
        if (stage == 0) {
            v0 = e.x; v1 = e.y;
        } else {
            float den = e.x * sw[2 * c] + e.y * sw[2 * c + 1];
            float ib = 1.0f / den;
            v0 = e.x * ib; v1 = e.y * ib;
        }
        switch (c) {
            case 0:  f0 += v0; f1 += v1; break;
            case 1:  f2 += v0; f3 += v1; break;
            case 2:  f4 += v0; f5 += v1; break;
            default: f6 += v0; f7 += v1; break;
        }
    }
    f0 = wsum(f0); f1 = wsum(f1); f2 = wsum(f2); f3 = wsum(f3);
    f4 = wsum(f4); f5 = wsum(f5); f6 = wsum(f6); f7 = wsum(f7);
    if ((tid & 31) == 0) {
        atomicAdd(&sred[0], f0); atomicAdd(&sred[1], f1);
        atomicAdd(&sred[2], f2); atomicAdd(&sred[3], f3);
        atomicAdd(&sred[4], f4); atomicAdd(&sred[5], f5);
        atomicAdd(&sred[6], f6); atomicAdd(&sred[7], f7);
    }
    __syncthreads();
    if (tid < 8) {
        double* dst = (stage == 0) ? g_E : (stage == 1) ? g_T2 : g_T3;
        atomicAdd(&dst[tid], (double)sred[tid]);
    }
}

// ---------------- K_target: proto_target + final assignment byte ----------------
__global__ void k_target(float* __restrict__ target) {
    __shared__ float sw[8];
    int tid = threadIdx.x;
    if (tid < 8) sw[tid] = (float)(1.0 / fmax(g_T3[tid], 1e-300));
    __syncthreads();
    int n = blockIdx.x * blockDim.x + tid;
    if (n >= NPIX) return;
    unsigned char code = g_code[n];
    int c = code & 3;
    float2 e = g_e[n];
    int idx = (e.y * sw[2 * c + 1] > e.x * sw[2 * c]) ? 1 : 0;   // ties -> 0
    target[n] = (float)(idx + 2 * c);
    g_ridx[n] = (code & 4) ? (unsigned char)(c * 2 + idx) : (unsigned char)255;
}

// ---------------- K_accum: masked feature sums, bucket-outermost, packed math ----------------
__global__ void __launch_bounds__(256) k_accum(
    const float* __restrict__ feat_in,
    const float* __restrict__ fg, const float* __restrict__ fb)
{
    __shared__ float sfacc[8][DIM];
    __shared__ int   scnt[8];
    int tid = threadIdx.x;
    for (int t = tid; t < 8 * DIM; t += 256) ((float*)sfacc)[t] = 0.f;
    if (tid < 8) scnt[tid] = 0;

    int w = tid >> 5, lane = tid & 31;
    const ulonglong2* fgp = (const ulonglong2*)fg;
    const ulonglong2* fbp = (const ulonglong2*)fb;
    ulonglong2 gA = fgp[lane], gB = fgp[lane + 32];
    ulonglong2 bA = fbp[lane], bB = fbp[lane + 32];
    u64 g2[4]  = {gA.x, gA.y, gB.x, gB.y};
    u64 be2[4] = {bA.x, bA.y, bB.x, bB.y};
    __syncthreads();

#pragma unroll 1
    for (int r = 0; r < 8; r++) {
        u64 acc2[4] = {0ull, 0ull, 0ull, 0ull};   // packed (0.f,0.f)
        int cnt = 0;
        for (int chunk = blockIdx.x * 8 + w; chunk < NCHUNK; chunk += gridDim.x * 8) {
            int n0 = chunk * 32;
            int rl = g_ridx[n0 + lane];
            unsigned mask = __ballot_sync(FULLW, rl == r);
            while (mask) {
                int j = __ffs(mask) - 1;
                mask &= mask - 1;
                int n = n0 + j;

                const ulonglong2* row = (const ulonglong2*)(feat_in + (size_t)n * DIM);
                ulonglong2 ra = row[lane], rb = row[lane + 32];
                u64 x2[4] = {ra.x, ra.y, rb.x, rb.y};
                u64 s2 = f2_add(f2_add(x2[0], x2[1]), f2_add(x2[2], x2[3]));
                u64 q2 = f2_mul(x2[0], x2[0]);
                q2 = f2_fma(x2[1], x2[1], q2);
                q2 = f2_fma(x2[2], x2[2], q2);
                q2 = f2_fma(x2[3], x2[3], q2);
                float s = f2_hadd(s2), ss = f2_hadd(q2);
                {
                    float v = (lane & 16) ? ss : s;
                    float o = (lane & 16) ? s : ss;
                    v += __shfl_xor_sync(FULLW, o, 16);
                    v += __shfl_xor_sync(FULLW, v, 8);
                    v += __shfl_xor_sync(FULLW, v, 4);
                    v += __shfl_xor_sync(FULLW, v, 2);
                    v += __shfl_xor_sync(FULLW, v, 1);
                    s  = __shfl_sync(FULLW, v, lane & 15);
                    ss = __shfl_sync(FULLW, v, (lane & 15) | 16);
                }
                float mu = s * (1.f / DIM), var = ss * (1.f / DIM) - mu * mu;
                float rstd = rsqrtf(var + 1e-5f);
                u64 A2 = f2_bcast(rstd), M2 = f2_bcast(-mu * rstd);
                u64 y2[4];
#pragma unroll
                for (int i = 0; i < 4; i++) {
                    u64 t = f2_fma(x2[i], A2, M2);
                    y2[i] = f2_fma(t, g2[i], be2[i]);
                }
                u64 n2 = f2_mul(y2[0], y2[0]);
                n2 = f2_fma(y2[1], y2[1], n2);
                n2 = f2_fma(y2[2], y2[2], n2);
                n2 = f2_fma(y2[3], y2[3], n2);
                float nrm = wsum(f2_hadd(n2));
                float inv = 1.f / fmaxf(sqrtf(nrm), 1e-12f);
                u64 I2 = f2_bcast(inv);
#pragma unroll
                for (int i = 0; i < 4; i++) acc2[i] = f2_fma(y2[i], I2, acc2[i]);
                cnt++;
            }
        }
        // flush bucket r
#pragma unroll
        for (int i = 0; i < 4; i++) {
            float lo, hi; f2_unpack(acc2[i], lo, hi);
            int base = (i < 2) ? (4 * lane + 2 * i) : (128 + 4 * lane + 2 * (i - 2));
            atomicAdd(&sfacc[r][base], lo);
            atomicAdd(&sfacc[r][base + 1], hi);
        }
        if (lane == 0) atomicAdd(&scnt[r], cnt);
    }
    __syncthreads();
    for (int t = tid; t < 8 * DIM; t += 256) atomicAdd(&((float*)g_facc)[t], ((float*)sfacc)[t]);
    if (tid < 8) atomicAdd(&g_cnt[tid], scnt[tid]);
}

// ---------------- K_final: EMA update + renormalize prototypes ----------------
__global__ void k_final(float* __restrict__ out) {
    int tid = threadIdx.x;
    int r = tid >> 5, lane = tid & 31;
    float f[8]; float ss = 0.f;
#pragma unroll
    for (int i = 0; i < 8; i++) { f[i] = g_facc[r][lane + 32 * i]; ss += f[i] * f[i]; }
    ss = wsum(ss);
    float inv = 1.f / fmaxf(sqrtf(ss), 1e-12f);
    int c = r >> 1;
    bool cond = ((g_cnt[c * 2] + g_cnt[c * 2 + 1]) > 0) && (g_cnt[r] != 0);
    float u[8]; float ss2 = 0.f;
#pragma unroll
    for (int i = 0; i < 8; i++) {
        float p = g_protos[r][lane + 32 * i];
        u[i] = cond ? (0.999f * p + 0.001f * (f[i] * inv)) : p;
        ss2 += u[i] * u[i];
    }
    ss2 = wsum(ss2);
    float inv2 = 1.f / fmaxf(sqrtf(ss2), 1e-12f);
    float* np = out + OUT_PROTOS;
#pragma unroll
    for (int i = 0; i < 8; i++) np[r * DIM + lane + 32 * i] = u[i] * inv2;
}

// ---------------- launch ----------------
extern "C" void kernel_launch(void* const* d_in, const int* in_sizes, int n_in,
                              void* d_out, int out_size)
{
    const float* feat   = (const float*)d_in[0];
    const int*   label  = (const int*)  d_in[1];
    const float* protos = (const float*)d_in[2];
    const float* fg     = (const float*)d_in[3];
    const float* fb     = (const float*)d_in[4];
    const float* mg     = (const float*)d_in[5];
    const float* mb     = (const float*)d_in[6];
    float* out = (float*)d_out;

    k_init<<<1, 256>>>(protos);
    k_main<<<1184, 256>>>(feat, label, fg, fb, mg, mb, out);
    k_R<<<1184, 256>>>(0);   // Σe  -> g_E
    k_R<<<1184, 256>>>(1);   //     -> g_T2
    k_R<<<1184, 256>>>(2);   //     -> g_T3
    k_target<<<NPIX / 256, 256>>>(out + OUT_TARGET);
    k_accum<<<1184, 256>>>(feat, fg, fb);
    k_final<<<1, 256>>>(out);
}

// round 14
// speedup vs baseline: 1.6960x; 1.0177x over previous
#include <cuda_runtime.h>
#include <math.h>

// Geometry (fixed by the problem)
#define NPIX   401408        // 32*112*112
#define DIM    256
#define NCLS   4
#define NSUB   2
#define IMG    12544         // 112*112
#define NCHUNK (NPIX / 32)   // 12544

// d_out layout: nearest_img | proto_logits | proto_target | new_protos
#define OUT_LOGITS  (NPIX * NCLS)                 // 1605632
#define OUT_TARGET  (OUT_LOGITS + NPIX * 8)       // 4816896
#define OUT_PROTOS  (OUT_TARGET + NPIX)           // 5218304

#define FULLW 0xffffffffu

typedef unsigned long long u64;

// ---------------- packed f32x2 helpers (Blackwell FFMA2 pipe) ----------------
__device__ __forceinline__ u64 f2_mul(u64 a, u64 b) {
    u64 r; asm("mul.rn.f32x2 %0, %1, %2;" : "=l"(r) : "l"(a), "l"(b)); return r;
}
__device__ __forceinline__ u64 f2_add(u64 a, u64 b) {
    u64 r; asm("add.rn.f32x2 %0, %1, %2;" : "=l"(r) : "l"(a), "l"(b)); return r;
}
__device__ __forceinline__ u64 f2_fma(u64 a, u64 b, u64 c) {
    u64 r; asm("fma.rn.f32x2 %0, %1, %2, %3;" : "=l"(r) : "l"(a), "l"(b), "l"(c)); return r;
}
__device__ __forceinline__ float f2_hadd(u64 a) {
    float lo, hi; asm("mov.b64 {%0, %1}, %2;" : "=f"(lo), "=f"(hi) : "l"(a)); return lo + hi;
}
__device__ __forceinline__ void f2_unpack(u64 a, float& lo, float& hi) {
    asm("mov.b64 {%0, %1}, %2;" : "=f"(lo), "=f"(hi) : "l"(a));
}
__device__ __forceinline__ u64 f2_bcast(float v) {
    u64 r; asm("mov.b64 %0, {%1, %1};" : "=l"(r) : "f"(v)); return r;
}

// ---------------- device scratch (no allocation allowed) ----------------
__device__ double        g_E[8];                 // Σ e_m per class   [c*2+m]
__device__ double        g_T2[8];                // iter-2 row sums
__device__ double        g_T3[8];                // iter-3 row sums
__device__ float         g_facc[8][DIM];         // masked feature sums [c*2+m][d]
__device__ int           g_cnt[8];               // assignment counts  [c*2+m]
__device__ float         g_protos[8][DIM];       // l2-normalized prototypes, row = k*2+m
__device__ float2        g_e[NPIX];              // (e0, e1) for the pixel's own class
__device__ unsigned char g_code[NPIX];           // bits 0-1: class, bit 2: correct
__device__ unsigned char g_ridx[NPIX];           // c*2+idx if correct else 255
__device__ float4        g_ln[NPIX];             // per-pixel (a, b, inv, 0): y*inv = g*(a*x+b) + be*inv

__device__ __forceinline__ float wsum(float v) {
#pragma unroll
    for (int o = 16; o; o >>= 1) v += __shfl_xor_sync(FULLW, v, o);
    return v;
}

// value-folding reduction step
__device__ __forceinline__ void fold2(float& a, float b, int off, int lane) {
    bool hi = (lane & off) != 0;
    float keep = hi ? b : a;
    float send = hi ? a : b;
    a = keep + __shfl_xor_sync(FULLW, send, off);
}

// ---------------- K0: zero scratch + normalize prototypes ----------------
__global__ void k_init(const float* __restrict__ protos) {
    int tid = threadIdx.x;
    if (tid < 8)  { g_E[tid] = 0.0; g_T2[tid] = 0.0; g_T3[tid] = 0.0; g_cnt[tid] = 0; }
    for (int t = tid; t < 8 * DIM; t += blockDim.x) ((float*)g_facc)[t] = 0.f;

    int w = tid >> 5, lane = tid & 31;
    float p[8]; float ss = 0.f;
#pragma unroll
    for (int i = 0; i < 8; i++) { p[i] = protos[w * DIM + lane + 32 * i]; ss += p[i] * p[i]; }
    ss = wsum(ss);
    float inv = 1.0f / fmaxf(sqrtf(ss), 1e-12f);
#pragma unroll
    for (int i = 0; i < 8; i++) g_protos[w][lane + 32 * i] = p[i] * inv;
}

// ---------------- K1: main fused pass over out_feat (packed f32x2) ----------------
__global__ void __launch_bounds__(256) k_main(
    const float* __restrict__ feat_in, const int* __restrict__ label,
    const float* __restrict__ fg, const float* __restrict__ fb,
    const float* __restrict__ mg, const float* __restrict__ mb,
    float* __restrict__ out)
{
    __shared__ float sprot[8][DIM];
    __shared__ float smg[4], smb[4];
    __shared__ float stage[4][32];

    int tid = threadIdx.x;
    for (int t = tid; t < 8 * DIM; t += 256) ((float*)sprot)[t] = ((const float*)g_protos)[t];
    if (tid < 4) { smg[tid] = mg[tid]; smb[tid] = mb[tid]; }

    int w = tid >> 5, lane = tid & 31;

    // packed per-lane gamma/beta (elements 4*lane.., 128+4*lane..)
    const ulonglong2* fgp = (const ulonglong2*)fg;
    const ulonglong2* fbp = (const ulonglong2*)fb;
    ulonglong2 gA = fgp[lane], gB = fgp[lane + 32];
    ulonglong2 bA = fbp[lane], bB = fbp[lane + 32];
    u64 g2[4]  = {gA.x, gA.y, gB.x, gB.y};
    u64 be2[4] = {bA.x, bA.y, bB.x, bB.y};
    __syncthreads();

    float* logits = out + OUT_LOGITS;

    for (int chunk = blockIdx.x; chunk < NCHUNK; chunk += gridDim.x) {
#pragma unroll 1
        for (int p = 0; p < 4; p++) {
            int n = chunk * 32 + w * 4 + p;
            const ulonglong2* row = (const ulonglong2*)(feat_in + (size_t)n * DIM);
            ulonglong2 ra = row[lane], rb = row[lane + 32];
            u64 x2[4] = {ra.x, ra.y, rb.x, rb.y};

            // packed sums
            u64 s2 = f2_add(f2_add(x2[0], x2[1]), f2_add(x2[2], x2[3]));
            u64 q2 = f2_mul(x2[0], x2[0]);
            q2 = f2_fma(x2[1], x2[1], q2);
            q2 = f2_fma(x2[2], x2[2], q2);
            q2 = f2_fma(x2[3], x2[3], q2);
            float s = f2_hadd(s2), ss = f2_hadd(q2);
            // folded (s,ss) reduction: 7 shuffles
            {
                float v = (lane & 16) ? ss : s;
                float o = (lane & 16) ? s : ss;
                v += __shfl_xor_sync(FULLW, o, 16);
                v += __shfl_xor_sync(FULLW, v, 8);
                v += __shfl_xor_sync(FULLW, v, 4);
                v += __shfl_xor_sync(FULLW, v, 2);
                v += __shfl_xor_sync(FULLW, v, 1);
                s  = __shfl_sync(FULLW, v, lane & 15);
                ss = __shfl_sync(FULLW, v, (lane & 15) | 16);
            }
            float mu = s * (1.f / DIM);
            float var = ss * (1.f / DIM) - mu * mu;
            float rstd = rsqrtf(var + 1e-5f);

            // LN transform (packed): y = (x*rstd - mu*rstd)*g + be
            u64 A2 = f2_bcast(rstd), M2 = f2_bcast(-mu * rstd);
            u64 y2[4];
#pragma unroll
            for (int i = 0; i < 4; i++) {
                u64 t = f2_fma(x2[i], A2, M2);
                y2[i] = f2_fma(t, g2[i], be2[i]);
            }
            // raw norm (reduced in parallel with dot folds; inv applied post-reduction)
            u64 n2 = f2_mul(y2[0], y2[0]);
            n2 = f2_fma(y2[1], y2[1], n2);
            n2 = f2_fma(y2[2], y2[2], n2);
            n2 = f2_fma(y2[3], y2[3], n2);
            float nrm = f2_hadd(n2);

            // raw dots (packed)
            float d0, d1, d2, d3, d4, d5, d6, d7;
            {
                float dd[8];
#pragma unroll
                for (int j = 0; j < 8; j++) {
                    const ulonglong2* p4 = (const ulonglong2*)sprot[j];
                    ulonglong2 pa = p4[lane], pb = p4[lane + 32];
                    u64 a2 = f2_mul(y2[0], pa.x);
                    a2 = f2_fma(y2[1], pa.y, a2);
                    a2 = f2_fma(y2[2], pb.x, a2);
                    a2 = f2_fma(y2[3], pb.y, a2);
                    dd[j] = f2_hadd(a2);
                }
                d0 = dd[0]; d1 = dd[1]; d2 = dd[2]; d3 = dd[3];
                d4 = dd[4]; d5 = dd[5]; d6 = dd[6]; d7 = dd[7];
            }
            nrm = wsum(nrm);                         // independent chain -> ILP
            float inv = 1.0f / fmaxf(sqrtf(nrm), 1e-12f);

            // folded 8-value reduction: lane 4j ends with full raw dot[j]
            fold2(d0, d4, 16, lane);
            fold2(d1, d5, 16, lane);
            fold2(d2, d6, 16, lane);
            fold2(d3, d7, 16, lane);
            fold2(d0, d2, 8, lane);
            fold2(d1, d3, 8, lane);
            fold2(d0, d1, 4, lane);
            d0 += __shfl_xor_sync(FULLW, d0, 2);
            d0 += __shfl_xor_sync(FULLW, d0, 1);
            d0 *= inv;                               // l2-normalization applied once

            // direct permuted logits store: lane 4j holds dot j = dot[k*2+m]
            if ((lane & 3) == 0) {
                int j = lane >> 2;
                int slot = ((j & 1) << 2) | (j >> 1);
                logits[(size_t)n * 8 + slot] = d0;
            }

            // gather all 8 dots to every lane
            float dt0 = __shfl_sync(FULLW, d0, 0);
            float dt1 = __shfl_sync(FULLW, d0, 4);
            float dt2 = __shfl_sync(FULLW, d0, 8);
            float dt3 = __shfl_sync(FULLW, d0, 12);
            float dt4 = __shfl_sync(FULLW, d0, 16);
            float dt5 = __shfl_sync(FULLW, d0, 20);
            float dt6 = __shfl_sync(FULLW, d0, 24);
            float dt7 = __shfl_sync(FULLW, d0, 28);

            // tail on ALL lanes (divergence-free)
            float nr0 = fmaxf(dt0, dt1), nr1 = fmaxf(dt2, dt3);
            float nr2 = fmaxf(dt4, dt5), nr3 = fmaxf(dt6, dt7);
            float m4 = 0.25f * (nr0 + nr1 + nr2 + nr3);
            float v4 = 0.25f * (nr0*nr0 + nr1*nr1 + nr2*nr2 + nr3*nr3) - m4 * m4;
            float r4 = rsqrtf(v4 + 1e-5f);
            float no0 = (nr0 - m4) * r4 * smg[0] + smb[0];
            float no1 = (nr1 - m4) * r4 * smg[1] + smb[1];
            float no2 = (nr2 - m4) * r4 * smg[2] + smb[2];
            float no3 = (nr3 - m4) * r4 * smg[3] + smb[3];
            int pred = 0; float best = no0;
            if (no1 > best) { best = no1; pred = 1; }
            if (no2 > best) { best = no2; pred = 2; }
            if (no3 > best) { best = no3; pred = 3; }
            int c = label[n];
            float e0d = (c == 0) ? dt0 : (c == 1) ? dt2 : (c == 2) ? dt4 : dt6;
            float e1d = (c == 0) ? dt1 : (c == 1) ? dt3 : (c == 2) ? dt5 : dt7;
            float e0 = expf(e0d * 20.0f);   // /SK_EPS
            float e1 = expf(e1d * 20.0f);

            if (lane == 0) {
                g_e[n] = make_float2(e0, e1);
                g_code[n] = (unsigned char)(c | ((pred == c) << 2));
                // per-pixel LN scalars for k_accum: y*inv = g*(a*x + b) + be*inv
                float a_s = rstd * inv;
                g_ln[n] = make_float4(a_s, -mu * a_s, inv, 0.f);
                stage[0][w * 4 + p] = no0;
                stage[1][w * 4 + p] = no1;
                stage[2][w * 4 + p] = no2;
                stage[3][w * 4 + p] = no3;
            }
        }
        __syncthreads();
        // nearest_img[b,k,h,w]: 32-pixel chunks never cross b (32 | 12544)
        if (tid < 128) {
            int k = tid >> 5, i = tid & 31;
            int base = chunk * 32;
            int b = base / IMG;
            int off = base - b * IMG + i;
            out[(size_t)b * 4 * IMG + (size_t)k * IMG + off] = stage[k][i];
        }
        __syncthreads();
    }
}

// ---------------- K_R: sinkhorn reductions (stage 0 -> E, 1 -> T2, 2 -> T3) ----------------
__global__ void __launch_bounds__(256) k_R(int stage) {
    __shared__ float sw[8];
    __shared__ float sred[8];
    int tid = threadIdx.x;
    if (tid < 8) {
        double src = (stage == 1) ? g_E[tid] : g_T2[tid];
        sw[tid] = (float)(1.0 / fmax(src, 1e-300));
        sred[tid] = 0.f;
    }
    __syncthreads();

    float f0 = 0.f, f1 = 0.f, f2 = 0.f, f3 = 0.f, f4 = 0.f, f5 = 0.f, f6 = 0.f, f7 = 0.f;

    int stride = gridDim.x * blockDim.x;
    for (int n = blockIdx.x * blockDim.x + tid; n < NPIX; n += stride) {
        int c = g_code[n] & 3;
        float2 e = g_e[n];
        float v0, v1;
        if (stage == 0) {
            v0 = e.x; v1 = e.y;
        } else {
            float den = e.x * sw[2 * c] + e.y * sw[2 * c + 1];
            float ib = 1.0f / den;
            v0 = e.x * ib; v1 = e.y * ib;
        }
        switch (c) {
            case 0:  f0 += v0; f1 += v1; break;
            case 1:  f2 += v0; f3 += v1; break;
            case 2:  f4 += v0; f5 += v1; break;
            default: f6 += v0; f7 += v1; break;
        }
    }
    f0 = wsum(f0); f1 = wsum(f1); f2 = wsum(f2); f3 = wsum(f3);
    f4 = wsum(f4); f5 = wsum(f5); f6 = wsum(f6); f7 = wsum(f7);
    if ((tid & 31) == 0) {
        atomicAdd(&sred[0], f0); atomicAdd(&sred[1], f1);
        atomicAdd(&sred[2], f2); atomicAdd(&sred[3], f3);
        atomicAdd(&sred[4], f4); atomicAdd(&sred[5], f5);
        atomicAdd(&sred[6], f6); atomicAdd(&sred[7], f7);
    }
    __syncthreads();
    if (tid < 8) {
        double* dst = (stage == 0) ? g_E : (stage == 1) ? g_T2 : g_T3;
        atomicAdd(&dst[tid], (double)sred[tid]);
    }
}

// ---------------- K_target: proto_target + final assignment byte ----------------
__global__ void k_target(float* __restrict__ target) {
    __shared__ float sw[8];
    int tid = threadIdx.x;
    if (tid < 8) sw[tid] = (float)(1.0 / fmax(g_T3[tid], 1e-300));
    __syncthreads();
    int n = blockIdx.x * blockDim.x + tid;
    if (n >= NPIX) return;
    unsigned char code = g_code[n];
    int c = code & 3;
    float2 e = g_e[n];
    int idx = (e.y * sw[2 * c + 1] > e.x * sw[2 * c]) ? 1 : 0;   // ties -> 0
    target[n] = (float)(idx + 2 * c);
    g_ridx[n] = (code & 4) ? (unsigned char)(c * 2 + idx) : (unsigned char)255;
}

// ---------------- K_accum: masked feature sums via precomputed LN scalars ----------------
// bucket sum = g_d*(Σ a_n x_nd + Σ b_n) + be_d * Σ inv_n  -- no per-row LN work
__global__ void __launch_bounds__(256) k_accum(
    const float* __restrict__ feat_in,
    const float* __restrict__ fg, const float* __restrict__ fb)
{
    __shared__ float sfacc[8][DIM];
    __shared__ int   scnt[8];
    int tid = threadIdx.x;
    for (int t = tid; t < 8 * DIM; t += 256) ((float*)sfacc)[t] = 0.f;
    if (tid < 8) scnt[tid] = 0;

    int w = tid >> 5, lane = tid & 31;
    const ulonglong2* fgp = (const ulonglong2*)fg;
    const ulonglong2* fbp = (const ulonglong2*)fb;
    ulonglong2 gA = fgp[lane], gB = fgp[lane + 32];
    ulonglong2 bA = fbp[lane], bB = fbp[lane + 32];
    u64 g2[4]  = {gA.x, gA.y, gB.x, gB.y};
    u64 be2[4] = {bA.x, bA.y, bB.x, bB.y};
    __syncthreads();

#pragma unroll 1
    for (int r = 0; r < 8; r++) {
        u64 acc2[4] = {0ull, 0ull, 0ull, 0ull};   // packed Σ a_n*x_nd
        float sb = 0.f, sinv = 0.f;
        int cnt = 0;
        for (int chunk = blockIdx.x * 8 + w; chunk < NCHUNK; chunk += gridDim.x * 8) {
            int n0 = chunk * 32;
            int rl = g_ridx[n0 + lane];
            unsigned mask = __ballot_sync(FULLW, rl == r);
            while (mask) {
                int j = __ffs(mask) - 1;
                mask &= mask - 1;
                int n = n0 + j;

                float4 ln = g_ln[n];                 // broadcast load (same addr all lanes)
                const ulonglong2* row = (const ulonglong2*)(feat_in + (size_t)n * DIM);
                ulonglong2 ra = row[lane], rb = row[lane + 32];
                u64 A2 = f2_bcast(ln.x);
                acc2[0] = f2_fma(ra.x, A2, acc2[0]);
                acc2[1] = f2_fma(ra.y, A2, acc2[1]);
                acc2[2] = f2_fma(rb.x, A2, acc2[2]);
                acc2[3] = f2_fma(rb.y, A2, acc2[3]);
                sb += ln.y; sinv += ln.z; cnt++;
            }
        }
        // flush bucket r: val = g*(acc + sb) + be*sinv   (packed)
        u64 SB2 = f2_bcast(sb), SI2 = f2_bcast(sinv);
#pragma unroll
        for (int i = 0; i < 4; i++) {
            u64 t = f2_add(acc2[i], SB2);
            t = f2_mul(t, g2[i]);
            t = f2_fma(be2[i], SI2, t);
            float lo, hi; f2_unpack(t, lo, hi);
            int base = (i < 2) ? (4 * lane + 2 * i) : (128 + 4 * lane + 2 * (i - 2));
            atomicAdd(&sfacc[r][base], lo);
            atomicAdd(&sfacc[r][base + 1], hi);
        }
        if (lane == 0) atomicAdd(&scnt[r], cnt);
    }
    __syncthreads();
    for (int t = tid; t < 8 * DIM; t += 256) atomicAdd(&((float*)g_facc)[t], ((float*)sfacc)[t]);
    if (tid < 8) atomicAdd(&g_cnt[tid], scnt[tid]);
}

// ---------------- K_final: EMA update + renormalize prototypes ----------------
__global__ void k_final(float* __restrict__ out) {
    int tid = threadIdx.x;
    int r = tid >> 5, lane = tid & 31;
    float f[8]; float ss = 0.f;
#pragma unroll
    for (int i = 0; i < 8; i++) { f[i] = g_facc[r][lane + 32 * i]; ss += f[i] * f[i]; }
    ss = wsum(ss);
    float inv = 1.f / fmaxf(sqrtf(ss), 1e-12f);
    int c = r >> 1;
    bool cond = ((g_cnt[c * 2] + g_cnt[c * 2 + 1]) > 0) && (g_cnt[r] != 0);
    float u[8]; float ss2 = 0.f;
#pragma unroll
    for (int i = 0; i < 8; i++) {
        float p = g_protos[r][lane + 32 * i];
        u[i] = cond ? (0.999f * p + 0.001f * (f[i] * inv)) : p;
        ss2 += u[i] * u[i];
    }
    ss2 = wsum(ss2);
    float inv2 = 1.f / fmaxf(sqrtf(ss2), 1e-12f);
    float* np = out + OUT_PROTOS;
#pragma unroll
    for (int i = 0; i < 8; i++) np[r * DIM + lane + 32 * i] = u[i] * inv2;
}

// ---------------- launch ----------------
extern "C" void kernel_launch(void* const* d_in, const int* in_sizes, int n_in,
                              void* d_out, int out_size)
{
    const float* feat   = (const float*)d_in[0];
    const int*   label  = (const int*)  d_in[1];
    const float* protos = (const float*)d_in[2];
    const float* fg     = (const float*)d_in[3];
    const float* fb     = (const float*)d_in[4];
    const float* mg     = (const float*)d_in[5];
    const float* mb     = (const float*)d_in[6];
    float* out = (float*)d_out;

    k_init<<<1, 256>>>(protos);
    k_main<<<1184, 256>>>(feat, label, fg, fb, mg, mb, out);
    k_R<<<1184, 256>>>(0);   // Σe  -> g_E
    k_R<<<1184, 256>>>(1);   //     -> g_T2
    k_R<<<1184, 256>>>(2);   //     -> g_T3
    k_target<<<NPIX / 256, 256>>>(out + OUT_TARGET);
    k_accum<<<1184, 256>>>(feat, fg, fb);
    k_final<<<1, 256>>>(out);
}

// round 15
// speedup vs baseline: 1.7148x; 1.0111x over previous
#include <cuda_runtime.h>
#include <math.h>

// Geometry (fixed by the problem)
#define NPIX   401408        // 32*112*112
#define DIM    256
#define NCLS   4
#define NSUB   2
#define IMG    12544         // 112*112
#define NCHUNK (NPIX / 32)   // 12544

// d_out layout: nearest_img | proto_logits | proto_target | new_protos
#define OUT_LOGITS  (NPIX * NCLS)                 // 1605632
#define OUT_TARGET  (OUT_LOGITS + NPIX * 8)       // 4816896
#define OUT_PROTOS  (OUT_TARGET + NPIX)           // 5218304

#define FULLW 0xffffffffu

typedef unsigned long long u64;

// ---------------- packed f32x2 helpers (Blackwell FFMA2 pipe) ----------------
__device__ __forceinline__ u64 f2_mul(u64 a, u64 b) {
    u64 r; asm("mul.rn.f32x2 %0, %1, %2;" : "=l"(r) : "l"(a), "l"(b)); return r;
}
__device__ __forceinline__ u64 f2_add(u64 a, u64 b) {
    u64 r; asm("add.rn.f32x2 %0, %1, %2;" : "=l"(r) : "l"(a), "l"(b)); return r;
}
__device__ __forceinline__ u64 f2_fma(u64 a, u64 b, u64 c) {
    u64 r; asm("fma.rn.f32x2 %0, %1, %2, %3;" : "=l"(r) : "l"(a), "l"(b), "l"(c)); return r;
}
__device__ __forceinline__ float f2_hadd(u64 a) {
    float lo, hi; asm("mov.b64 {%0, %1}, %2;" : "=f"(lo), "=f"(hi) : "l"(a)); return lo + hi;
}
__device__ __forceinline__ void f2_unpack(u64 a, float& lo, float& hi) {
    asm("mov.b64 {%0, %1}, %2;" : "=f"(lo), "=f"(hi) : "l"(a));
}
__device__ __forceinline__ u64 f2_bcast(float v) {
    u64 r; asm("mov.b64 %0, {%1, %1};" : "=l"(r) : "f"(v)); return r;
}

// ---------------- device scratch (no allocation allowed) ----------------
__device__ double        g_E[8];                 // Σ e_m per class   [c*2+m]
__device__ double        g_T2[8];                // iter-2 row sums
__device__ double        g_T3[8];                // iter-3 row sums
__device__ float         g_facc[8][DIM];         // masked feature sums [c*2+m][d]
__device__ int           g_cnt[8];               // assignment counts  [c*2+m]
__device__ float         g_protos[8][DIM];       // l2-normalized prototypes, row = k*2+m
__device__ float2        g_e[NPIX];              // (e0, e1) for the pixel's own class
__device__ unsigned char g_code[NPIX];           // bits 0-1: class, bit 2: correct
__device__ float4        g_ln[NPIX];             // per-pixel (a, b, inv, 0)

__device__ __forceinline__ float wsum(float v) {
#pragma unroll
    for (int o = 16; o; o >>= 1) v += __shfl_xor_sync(FULLW, v, o);
    return v;
}

// value-folding reduction step
__device__ __forceinline__ void fold2(float& a, float b, int off, int lane) {
    bool hi = (lane & off) != 0;
    float keep = hi ? b : a;
    float send = hi ? a : b;
    a = keep + __shfl_xor_sync(FULLW, send, off);
}

// ---------------- K0: zero scratch + normalize prototypes ----------------
__global__ void k_init(const float* __restrict__ protos) {
    int tid = threadIdx.x;
    if (tid < 8)  { g_E[tid] = 0.0; g_T2[tid] = 0.0; g_T3[tid] = 0.0; g_cnt[tid] = 0; }
    for (int t = tid; t < 8 * DIM; t += blockDim.x) ((float*)g_facc)[t] = 0.f;

    int w = tid >> 5, lane = tid & 31;
    float p[8]; float ss = 0.f;
#pragma unroll
    for (int i = 0; i < 8; i++) { p[i] = protos[w * DIM + lane + 32 * i]; ss += p[i] * p[i]; }
    ss = wsum(ss);
    float inv = 1.0f / fmaxf(sqrtf(ss), 1e-12f);
#pragma unroll
    for (int i = 0; i < 8; i++) g_protos[w][lane + 32 * i] = p[i] * inv;
}

// ---------------- K1: main fused pass over out_feat (packed f32x2) ----------------
__global__ void __launch_bounds__(256) k_main(
    const float* __restrict__ feat_in, const int* __restrict__ label,
    const float* __restrict__ fg, const float* __restrict__ fb,
    const float* __restrict__ mg, const float* __restrict__ mb,
    float* __restrict__ out)
{
    __shared__ float sprot[8][DIM];
    __shared__ float smg[4], smb[4];
    __shared__ float stage[4][32];

    int tid = threadIdx.x;
    for (int t = tid; t < 8 * DIM; t += 256) ((float*)sprot)[t] = ((const float*)g_protos)[t];
    if (tid < 4) { smg[tid] = mg[tid]; smb[tid] = mb[tid]; }

    int w = tid >> 5, lane = tid & 31;

    // packed per-lane gamma/beta (elements 4*lane.., 128+4*lane..)
    const ulonglong2* fgp = (const ulonglong2*)fg;
    const ulonglong2* fbp = (const ulonglong2*)fb;
    ulonglong2 gA = fgp[lane], gB = fgp[lane + 32];
    ulonglong2 bA = fbp[lane], bB = fbp[lane + 32];
    u64 g2[4]  = {gA.x, gA.y, gB.x, gB.y};
    u64 be2[4] = {bA.x, bA.y, bB.x, bB.y};
    __syncthreads();

    float* logits = out + OUT_LOGITS;

    for (int chunk = blockIdx.x; chunk < NCHUNK; chunk += gridDim.x) {
#pragma unroll 1
        for (int p = 0; p < 4; p++) {
            int n = chunk * 32 + w * 4 + p;
            const ulonglong2* row = (const ulonglong2*)(feat_in + (size_t)n * DIM);
            ulonglong2 ra = row[lane], rb = row[lane + 32];
            u64 x2[4] = {ra.x, ra.y, rb.x, rb.y};

            // packed sums
            u64 s2 = f2_add(f2_add(x2[0], x2[1]), f2_add(x2[2], x2[3]));
            u64 q2 = f2_mul(x2[0], x2[0]);
            q2 = f2_fma(x2[1], x2[1], q2);
            q2 = f2_fma(x2[2], x2[2], q2);
            q2 = f2_fma(x2[3], x2[3], q2);
            float s = f2_hadd(s2), ss = f2_hadd(q2);
            // folded (s,ss) reduction: 7 shuffles
            {
                float v = (lane & 16) ? ss : s;
                float o = (lane & 16) ? s : ss;
                v += __shfl_xor_sync(FULLW, o, 16);
                v += __shfl_xor_sync(FULLW, v, 8);
                v += __shfl_xor_sync(FULLW, v, 4);
                v += __shfl_xor_sync(FULLW, v, 2);
                v += __shfl_xor_sync(FULLW, v, 1);
                s  = __shfl_sync(FULLW, v, lane & 15);
                ss = __shfl_sync(FULLW, v, (lane & 15) | 16);
            }
            float mu = s * (1.f / DIM);
            float var = ss * (1.f / DIM) - mu * mu;
            float rstd = rsqrtf(var + 1e-5f);

            // LN transform (packed): y = (x*rstd - mu*rstd)*g + be
            u64 A2 = f2_bcast(rstd), M2 = f2_bcast(-mu * rstd);
            u64 y2[4];
#pragma unroll
            for (int i = 0; i < 4; i++) {
                u64 t = f2_fma(x2[i], A2, M2);
                y2[i] = f2_fma(t, g2[i], be2[i]);
            }
            // raw norm (reduced in parallel with dot folds; inv applied post-reduction)
            u64 n2 = f2_mul(y2[0], y2[0]);
            n2 = f2_fma(y2[1], y2[1], n2);
            n2 = f2_fma(y2[2], y2[2], n2);
            n2 = f2_fma(y2[3], y2[3], n2);
            float nrm = f2_hadd(n2);

            // raw dots (packed)
            float d0, d1, d2, d3, d4, d5, d6, d7;
            {
                float dd[8];
#pragma unroll
                for (int j = 0; j < 8; j++) {
                    const ulonglong2* p4 = (const ulonglong2*)sprot[j];
                    ulonglong2 pa = p4[lane], pb = p4[lane + 32];
                    u64 a2 = f2_mul(y2[0], pa.x);
                    a2 = f2_fma(y2[1], pa.y, a2);
                    a2 = f2_fma(y2[2], pb.x, a2);
                    a2 = f2_fma(y2[3], pb.y, a2);
                    dd[j] = f2_hadd(a2);
                }
                d0 = dd[0]; d1 = dd[1]; d2 = dd[2]; d3 = dd[3];
                d4 = dd[4]; d5 = dd[5]; d6 = dd[6]; d7 = dd[7];
            }
            nrm = wsum(nrm);                         // independent chain -> ILP
            float inv = 1.0f / fmaxf(sqrtf(nrm), 1e-12f);

            // folded 8-value reduction: lane 4j ends with full raw dot[j]
            fold2(d0, d4, 16, lane);
            fold2(d1, d5, 16, lane);
            fold2(d2, d6, 16, lane);
            fold2(d3, d7, 16, lane);
            fold2(d0, d2, 8, lane);
            fold2(d1, d3, 8, lane);
            fold2(d0, d1, 4, lane);
            d0 += __shfl_xor_sync(FULLW, d0, 2);
            d0 += __shfl_xor_sync(FULLW, d0, 1);
            d0 *= inv;                               // l2-normalization applied once

            // direct permuted logits store: lane 4j holds dot j = dot[k*2+m]
            if ((lane & 3) == 0) {
                int j = lane >> 2;
                int slot = ((j & 1) << 2) | (j >> 1);
                logits[(size_t)n * 8 + slot] = d0;
            }

            // gather all 8 dots to every lane
            float dt0 = __shfl_sync(FULLW, d0, 0);
            float dt1 = __shfl_sync(FULLW, d0, 4);
            float dt2 = __shfl_sync(FULLW, d0, 8);
            float dt3 = __shfl_sync(FULLW, d0, 12);
            float dt4 = __shfl_sync(FULLW, d0, 16);
            float dt5 = __shfl_sync(FULLW, d0, 20);
            float dt6 = __shfl_sync(FULLW, d0, 24);
            float dt7 = __shfl_sync(FULLW, d0, 28);

            // tail on ALL lanes (divergence-free)
            float nr0 = fmaxf(dt0, dt1), nr1 = fmaxf(dt2, dt3);
            float nr2 = fmaxf(dt4, dt5), nr3 = fmaxf(dt6, dt7);
            float m4 = 0.25f * (nr0 + nr1 + nr2 + nr3);
            float v4 = 0.25f * (nr0*nr0 + nr1*nr1 + nr2*nr2 + nr3*nr3) - m4 * m4;
            float r4 = rsqrtf(v4 + 1e-5f);
            float no0 = (nr0 - m4) * r4 * smg[0] + smb[0];
            float no1 = (nr1 - m4) * r4 * smg[1] + smb[1];
            float no2 = (nr2 - m4) * r4 * smg[2] + smb[2];
            float no3 = (nr3 - m4) * r4 * smg[3] + smb[3];
            int pred = 0; float best = no0;
            if (no1 > best) { best = no1; pred = 1; }
            if (no2 > best) { best = no2; pred = 2; }
            if (no3 > best) { best = no3; pred = 3; }
            int c = label[n];
            float e0d = (c == 0) ? dt0 : (c == 1) ? dt2 : (c == 2) ? dt4 : dt6;
            float e1d = (c == 0) ? dt1 : (c == 1) ? dt3 : (c == 2) ? dt5 : dt7;
            float e0 = expf(e0d * 20.0f);   // /SK_EPS
            float e1 = expf(e1d * 20.0f);

            if (lane == 0) {
                g_e[n] = make_float2(e0, e1);
                g_code[n] = (unsigned char)(c | ((pred == c) << 2));
                // per-pixel LN scalars for k_accum: y*inv = g*(a*x + b) + be*inv
                float a_s = rstd * inv;
                g_ln[n] = make_float4(a_s, -mu * a_s, inv, 0.f);
                stage[0][w * 4 + p] = no0;
                stage[1][w * 4 + p] = no1;
                stage[2][w * 4 + p] = no2;
                stage[3][w * 4 + p] = no3;
            }
        }
        __syncthreads();
        // nearest_img[b,k,h,w]: 32-pixel chunks never cross b (32 | 12544)
        if (tid < 128) {
            int k = tid >> 5, i = tid & 31;
            int base = chunk * 32;
            int b = base / IMG;
            int off = base - b * IMG + i;
            out[(size_t)b * 4 * IMG + (size_t)k * IMG + off] = stage[k][i];
        }
        __syncthreads();
    }
}

// ---------------- K_R: sinkhorn reductions (stage 0 -> E, 1 -> T2, 2 -> T3) ----------------
__global__ void __launch_bounds__(256) k_R(int stage) {
    __shared__ float sw[8];
    __shared__ float sred[8];
    int tid = threadIdx.x;
    if (tid < 8) {
        double src = (stage == 1) ? g_E[tid] : g_T2[tid];
        sw[tid] = (float)(1.0 / fmax(src, 1e-300));
        sred[tid] = 0.f;
    }
    __syncthreads();

    float f0 = 0.f, f1 = 0.f, f2 = 0.f, f3 = 0.f, f4 = 0.f, f5 = 0.f, f6 = 0.f, f7 = 0.f;

    int stride = gridDim.x * blockDim.x;
    for (int n = blockIdx.x * blockDim.x + tid; n < NPIX; n += stride) {
        int c = g_code[n] & 3;
        float2 e = g_e[n];
        float v0, v1;
        if (stage == 0) {
            v0 = e.x; v1 = e.y;
        } else {
            float den = e.x * sw[2 * c] + e.y * sw[2 * c + 1];
            float ib = 1.0f / den;
            v0 = e.x * ib; v1 = e.y * ib;
        }
        switch (c) {
            case 0:  f0 += v0; f1 += v1; break;
            case 1:  f2 += v0; f3 += v1; break;
            case 2:  f4 += v0; f5 += v1; break;
            default: f6 += v0; f7 += v1; break;
        }
    }
    f0 = wsum(f0); f1 = wsum(f1); f2 = wsum(f2); f3 = wsum(f3);
    f4 = wsum(f4); f5 = wsum(f5); f6 = wsum(f6); f7 = wsum(f7);
    if ((tid & 31) == 0) {
        atomicAdd(&sred[0], f0); atomicAdd(&sred[1], f1);
        atomicAdd(&sred[2], f2); atomicAdd(&sred[3], f3);
        atomicAdd(&sred[4], f4); atomicAdd(&sred[5], f5);
        atomicAdd(&sred[6], f6); atomicAdd(&sred[7], f7);
    }
    __syncthreads();
    if (tid < 8) {
        double* dst = (stage == 0) ? g_E : (stage == 1) ? g_T2 : g_T3;
        atomicAdd(&dst[tid], (double)sred[tid]);
    }
}

// ---------------- K_accum: target + masked feature sums (k_target merged) ----------------
// Phase 1: compute idx/ridx inline, write proto_target, cache ridx in smem.
// Phase 2: bucket-outermost accumulation via precomputed LN scalars.
__global__ void __launch_bounds__(256) k_accum(
    const float* __restrict__ feat_in,
    const float* __restrict__ fg, const float* __restrict__ fb,
    float* __restrict__ target)
{
    __shared__ float sfacc[8][DIM];
    __shared__ int   scnt[8];
    __shared__ float sw[8];
    __shared__ unsigned char sridx[8][2][32];
    int tid = threadIdx.x;
    for (int t = tid; t < 8 * DIM; t += 256) ((float*)sfacc)[t] = 0.f;
    if (tid < 8) {
        scnt[tid] = 0;
        sw[tid] = (float)(1.0 / fmax(g_T3[tid], 1e-300));
    }

    int w = tid >> 5, lane = tid & 31;
    const ulonglong2* fgp = (const ulonglong2*)fg;
    const ulonglong2* fbp = (const ulonglong2*)fb;
    ulonglong2 gA = fgp[lane], gB = fgp[lane + 32];
    ulonglong2 bA = fbp[lane], bB = fbp[lane + 32];
    u64 g2[4]  = {gA.x, gA.y, gB.x, gB.y};
    u64 be2[4] = {bA.x, bA.y, bB.x, bB.y};
    __syncthreads();

    int gw = blockIdx.x * 8 + w;             // grid=1184 -> gw in [0, 9472)
    const int WSTRIDE = 1184 * 8;            // 9472

    // ---- phase 1: target + ridx cache (each lane handles its own pixel) ----
#pragma unroll
    for (int it = 0; it < 2; it++) {
        int chunk = gw + WSTRIDE * it;
        if (chunk < NCHUNK) {
            int n = chunk * 32 + lane;
            unsigned char code = g_code[n];
            int c = code & 3;
            float2 e = g_e[n];
            int idx = (e.y * sw[2 * c + 1] > e.x * sw[2 * c]) ? 1 : 0;  // ties -> 0
            target[n] = (float)(idx + 2 * c);
            sridx[w][it][lane] = (code & 4) ? (unsigned char)(c * 2 + idx) : (unsigned char)255;
        }
    }
    // each lane wrote and reads only its own byte -> no sync needed

    // ---- phase 2: bucket-outermost accumulation ----
#pragma unroll 1
    for (int r = 0; r < 8; r++) {
        u64 acc2[4] = {0ull, 0ull, 0ull, 0ull};   // packed Σ a_n*x_nd
        float sb = 0.f, sinv = 0.f;
        int cnt = 0;
#pragma unroll
        for (int it = 0; it < 2; it++) {
            int chunk = gw + WSTRIDE * it;
            if (chunk < NCHUNK) {
                int n0 = chunk * 32;
                int rl = sridx[w][it][lane];
                unsigned mask = __ballot_sync(FULLW, rl == r);
                while (mask) {
                    int j = __ffs(mask) - 1;
                    mask &= mask - 1;
                    int n = n0 + j;

                    float4 ln = g_ln[n];             // broadcast load
                    const ulonglong2* row = (const ulonglong2*)(feat_in + (size_t)n * DIM);
                    ulonglong2 ra = row[lane], rb = row[lane + 32];
                    u64 A2 = f2_bcast(ln.x);
                    acc2[0] = f2_fma(ra.x, A2, acc2[0]);
                    acc2[1] = f2_fma(ra.y, A2, acc2[1]);
                    acc2[2] = f2_fma(rb.x, A2, acc2[2]);
                    acc2[3] = f2_fma(rb.y, A2, acc2[3]);
                    sb += ln.y; sinv += ln.z; cnt++;
                }
            }
        }
        // flush bucket r: val = g*(acc + sb) + be*sinv   (packed)
        u64 SB2 = f2_bcast(sb), SI2 = f2_bcast(sinv);
#pragma unroll
        for (int i = 0; i < 4; i++) {
            u64 t = f2_add(acc2[i], SB2);
            t = f2_mul(t, g2[i]);
            t = f2_fma(be2[i], SI2, t);
            float lo, hi; f2_unpack(t, lo, hi);
            int base = (i < 2) ? (4 * lane + 2 * i) : (128 + 4 * lane + 2 * (i - 2));
            atomicAdd(&sfacc[r][base], lo);
            atomicAdd(&sfacc[r][base + 1], hi);
        }
        if (lane == 0) atomicAdd(&scnt[r], cnt);
    }
    __syncthreads();
    for (int t = tid; t < 8 * DIM; t += 256) atomicAdd(&((float*)g_facc)[t], ((float*)sfacc)[t]);
    if (tid < 8) atomicAdd(&g_cnt[tid], scnt[tid]);
}

// ---------------- K_final: EMA update + renormalize prototypes ----------------
__global__ void k_final(float* __restrict__ out) {
    int tid = threadIdx.x;
    int r = tid >> 5, lane = tid & 31;
    float f[8]; float ss = 0.f;
#pragma unroll
    for (int i = 0; i < 8; i++) { f[i] = g_facc[r][lane + 32 * i]; ss += f[i] * f[i]; }
    ss = wsum(ss);
    float inv = 1.f / fmaxf(sqrtf(ss), 1e-12f);
    int c = r >> 1;
    bool cond = ((g_cnt[c * 2] + g_cnt[c * 2 + 1]) > 0) && (g_cnt[r] != 0);
    float u[8]; float ss2 = 0.f;
#pragma unroll
    for (int i = 0; i < 8; i++) {
        float p = g_protos[r][lane + 32 * i];
        u[i] = cond ? (0.999f * p + 0.001f * (f[i] * inv)) : p;
        ss2 += u[i] * u[i];
    }
    ss2 = wsum(ss2);
    float inv2 = 1.f / fmaxf(sqrtf(ss2), 1e-12f);
    float* np = out + OUT_PROTOS;
#pragma unroll
    for (int i = 0; i < 8; i++) np[r * DIM + lane + 32 * i] = u[i] * inv2;
}

// ---------------- launch ----------------
extern "C" void kernel_launch(void* const* d_in, const int* in_sizes, int n_in,
                              void* d_out, int out_size)
{
    const float* feat   = (const float*)d_in[0];
    const int*   label  = (const int*)  d_in[1];
    const float* protos = (const float*)d_in[2];
    const float* fg     = (const float*)d_in[3];
    const float* fb     = (const float*)d_in[4];
    const float* mg     = (const float*)d_in[5];
    const float* mb     = (const float*)d_in[6];
    float* out = (float*)d_out;

    k_init<<<1, 256>>>(protos);
    k_main<<<1184, 256>>>(feat, label, fg, fb, mg, mb, out);
    k_R<<<296, 256>>>(0);   // Σe  -> g_E
    k_R<<<296, 256>>>(1);   //     -> g_T2
    k_R<<<296, 256>>>(2);   //     -> g_T3
    k_accum<<<1184, 256>>>(feat, fg, fb, out + OUT_TARGET);
    k_final<<<1, 256>>>(out);
}

// round 16
// speedup vs baseline: 1.7394x; 1.0143x over previous
#include <cuda_runtime.h>
#include <math.h>

// Geometry (fixed by the problem)
#define NPIX   401408        // 32*112*112
#define DIM    256
#define NCLS   4
#define NSUB   2
#define IMG    12544         // 112*112
#define NCHUNK (NPIX / 32)   // 12544

// d_out layout: nearest_img | proto_logits | proto_target | new_protos
#define OUT_LOGITS  (NPIX * NCLS)                 // 1605632
#define OUT_TARGET  (OUT_LOGITS + NPIX * 8)       // 4816896
#define OUT_PROTOS  (OUT_TARGET + NPIX)           // 5218304

#define FULLW 0xffffffffu
#define SINK_GRID 296

typedef unsigned long long u64;

// ---------------- packed f32x2 helpers (Blackwell FFMA2 pipe) ----------------
__device__ __forceinline__ u64 f2_mul(u64 a, u64 b) {
    u64 r; asm("mul.rn.f32x2 %0, %1, %2;" : "=l"(r) : "l"(a), "l"(b)); return r;
}
__device__ __forceinline__ u64 f2_add(u64 a, u64 b) {
    u64 r; asm("add.rn.f32x2 %0, %1, %2;" : "=l"(r) : "l"(a), "l"(b)); return r;
}
__device__ __forceinline__ u64 f2_fma(u64 a, u64 b, u64 c) {
    u64 r; asm("fma.rn.f32x2 %0, %1, %2, %3;" : "=l"(r) : "l"(a), "l"(b), "l"(c)); return r;
}
__device__ __forceinline__ float f2_hadd(u64 a) {
    float lo, hi; asm("mov.b64 {%0, %1}, %2;" : "=f"(lo), "=f"(hi) : "l"(a)); return lo + hi;
}
__device__ __forceinline__ void f2_unpack(u64 a, float& lo, float& hi) {
    asm("mov.b64 {%0, %1}, %2;" : "=f"(lo), "=f"(hi) : "l"(a));
}
__device__ __forceinline__ u64 f2_bcast(float v) {
    u64 r; asm("mov.b64 %0, {%1, %1};" : "=l"(r) : "f"(v)); return r;
}

// ---------------- device scratch (no allocation allowed) ----------------
__device__ double        g_E[8];                 // Σ e_m per class   [c*2+m]
__device__ double        g_T2[8];                // iter-2 row sums
__device__ double        g_T3[8];                // iter-3 row sums
__device__ float         g_facc[8][DIM];         // masked feature sums [c*2+m][d]
__device__ int           g_cnt[8];               // assignment counts  [c*2+m]
__device__ float         g_protos[8][DIM];       // l2-normalized prototypes, row = k*2+m
__device__ float2        g_e[NPIX];              // (e0, e1) for the pixel's own class
__device__ unsigned char g_code[NPIX];           // bits 0-1: class, bit 2: correct
__device__ float4        g_ln[NPIX];             // per-pixel (a, b, inv, 0)
__device__ int           g_bar[2];               // grid-barrier counters (reset by k_init)

__device__ __forceinline__ float wsum(float v) {
#pragma unroll
    for (int o = 16; o; o >>= 1) v += __shfl_xor_sync(FULLW, v, o);
    return v;
}

// value-folding reduction step
__device__ __forceinline__ void fold2(float& a, float b, int off, int lane) {
    bool hi = (lane & off) != 0;
    float keep = hi ? b : a;
    float send = hi ? a : b;
    a = keep + __shfl_xor_sync(FULLW, send, off);
}

// ---------------- K0: zero scratch + normalize prototypes ----------------
__global__ void k_init(const float* __restrict__ protos) {
    int tid = threadIdx.x;
    if (tid < 8)  { g_E[tid] = 0.0; g_T2[tid] = 0.0; g_T3[tid] = 0.0; g_cnt[tid] = 0; }
    if (tid < 2)  g_bar[tid] = 0;
    for (int t = tid; t < 8 * DIM; t += blockDim.x) ((float*)g_facc)[t] = 0.f;

    int w = tid >> 5, lane = tid & 31;
    float p[8]; float ss = 0.f;
#pragma unroll
    for (int i = 0; i < 8; i++) { p[i] = protos[w * DIM + lane + 32 * i]; ss += p[i] * p[i]; }
    ss = wsum(ss);
    float inv = 1.0f / fmaxf(sqrtf(ss), 1e-12f);
#pragma unroll
    for (int i = 0; i < 8; i++) g_protos[w][lane + 32 * i] = p[i] * inv;
}

// ---------------- K1: main fused pass over out_feat (packed f32x2) ----------------
__global__ void __launch_bounds__(256) k_main(
    const float* __restrict__ feat_in, const int* __restrict__ label,
    const float* __restrict__ fg, const float* __restrict__ fb,
    const float* __restrict__ mg, const float* __restrict__ mb,
    float* __restrict__ out)
{
    __shared__ float sprot[8][DIM];
    __shared__ float smg[4], smb[4];
    __shared__ float stage[4][32];

    int tid = threadIdx.x;
    for (int t = tid; t < 8 * DIM; t += 256) ((float*)sprot)[t] = ((const float*)g_protos)[t];
    if (tid < 4) { smg[tid] = mg[tid]; smb[tid] = mb[tid]; }

    int w = tid >> 5, lane = tid & 31;

    // packed per-lane gamma/beta (elements 4*lane.., 128+4*lane..)
    const ulonglong2* fgp = (const ulonglong2*)fg;
    const ulonglong2* fbp = (const ulonglong2*)fb;
    ulonglong2 gA = fgp[lane], gB = fgp[lane + 32];
    ulonglong2 bA = fbp[lane], bB = fbp[lane + 32];
    u64 g2[4]  = {gA.x, gA.y, gB.x, gB.y};
    u64 be2[4] = {bA.x, bA.y, bB.x, bB.y};
    __syncthreads();

    float* logits = out + OUT_LOGITS;

    for (int chunk = blockIdx.x; chunk < NCHUNK; chunk += gridDim.x) {
#pragma unroll 1
        for (int p = 0; p < 4; p++) {
            int n = chunk * 32 + w * 4 + p;
            const ulonglong2* row = (const ulonglong2*)(feat_in + (size_t)n * DIM);
            ulonglong2 ra = row[lane], rb = row[lane + 32];
            u64 x2[4] = {ra.x, ra.y, rb.x, rb.y};

            // packed sums
            u64 s2 = f2_add(f2_add(x2[0], x2[1]), f2_add(x2[2], x2[3]));
            u64 q2 = f2_mul(x2[0], x2[0]);
            q2 = f2_fma(x2[1], x2[1], q2);
            q2 = f2_fma(x2[2], x2[2], q2);
            q2 = f2_fma(x2[3], x2[3], q2);
            float s = f2_hadd(s2), ss = f2_hadd(q2);
            // folded (s,ss) reduction: 7 shuffles
            {
                float v = (lane & 16) ? ss : s;
                float o = (lane & 16) ? s : ss;
                v += __shfl_xor_sync(FULLW, o, 16);
                v += __shfl_xor_sync(FULLW, v, 8);
                v += __shfl_xor_sync(FULLW, v, 4);
                v += __shfl_xor_sync(FULLW, v, 2);
                v += __shfl_xor_sync(FULLW, v, 1);
                s  = __shfl_sync(FULLW, v, lane & 15);
                ss = __shfl_sync(FULLW, v, (lane & 15) | 16);
            }
            float mu = s * (1.f / DIM);
            float var = ss * (1.f / DIM) - mu * mu;
            float rstd = rsqrtf(var + 1e-5f);

            // LN transform (packed): y = (x*rstd - mu*rstd)*g + be
            u64 A2 = f2_bcast(rstd), M2 = f2_bcast(-mu * rstd);
            u64 y2[4];
#pragma unroll
            for (int i = 0; i < 4; i++) {
                u64 t = f2_fma(x2[i], A2, M2);
                y2[i] = f2_fma(t, g2[i], be2[i]);
            }
            // raw norm (reduced in parallel with dot folds; inv applied post-reduction)
            u64 n2 = f2_mul(y2[0], y2[0]);
            n2 = f2_fma(y2[1], y2[1], n2);
            n2 = f2_fma(y2[2], y2[2], n2);
            n2 = f2_fma(y2[3], y2[3], n2);
            float nrm = f2_hadd(n2);

            // raw dots (packed)
            float d0, d1, d2, d3, d4, d5, d6, d7;
            {
                float dd[8];
#pragma unroll
                for (int j = 0; j < 8; j++) {
                    const ulonglong2* p4 = (const ulonglong2*)sprot[j];
                    ulonglong2 pa = p4[lane], pb = p4[lane + 32];
                    u64 a2 = f2_mul(y2[0], pa.x);
                    a2 = f2_fma(y2[1], pa.y, a2);
                    a2 = f2_fma(y2[2], pb.x, a2);
                    a2 = f2_fma(y2[3], pb.y, a2);
                    dd[j] = f2_hadd(a2);
                }
                d0 = dd[0]; d1 = dd[1]; d2 = dd[2]; d3 = dd[3];
                d4 = dd[4]; d5 = dd[5]; d6 = dd[6]; d7 = dd[7];
            }
            nrm = wsum(nrm);                         // independent chain -> ILP
            float inv = 1.0f / fmaxf(sqrtf(nrm), 1e-12f);

            // folded 8-value reduction: lane 4j ends with full raw dot[j]
            fold2(d0, d4, 16, lane);
            fold2(d1, d5, 16, lane);
            fold2(d2, d6, 16, lane);
            fold2(d3, d7, 16, lane);
            fold2(d0, d2, 8, lane);
            fold2(d1, d3, 8, lane);
            fold2(d0, d1, 4, lane);
            d0 += __shfl_xor_sync(FULLW, d0, 2);
            d0 += __shfl_xor_sync(FULLW, d0, 1);
            d0 *= inv;                               // l2-normalization applied once

            // direct permuted logits store: lane 4j holds dot j = dot[k*2+m]
            if ((lane & 3) == 0) {
                int j = lane >> 2;
                int slot = ((j & 1) << 2) | (j >> 1);
                logits[(size_t)n * 8 + slot] = d0;
            }

            // gather all 8 dots to every lane
            float dt0 = __shfl_sync(FULLW, d0, 0);
            float dt1 = __shfl_sync(FULLW, d0, 4);
            float dt2 = __shfl_sync(FULLW, d0, 8);
            float dt3 = __shfl_sync(FULLW, d0, 12);
            float dt4 = __shfl_sync(FULLW, d0, 16);
            float dt5 = __shfl_sync(FULLW, d0, 20);
            float dt6 = __shfl_sync(FULLW, d0, 24);
            float dt7 = __shfl_sync(FULLW, d0, 28);

            // tail on ALL lanes (divergence-free)
            float nr0 = fmaxf(dt0, dt1), nr1 = fmaxf(dt2, dt3);
            float nr2 = fmaxf(dt4, dt5), nr3 = fmaxf(dt6, dt7);
            float m4 = 0.25f * (nr0 + nr1 + nr2 + nr3);
            float v4 = 0.25f * (nr0*nr0 + nr1*nr1 + nr2*nr2 + nr3*nr3) - m4 * m4;
            float r4 = rsqrtf(v4 + 1e-5f);
            float no0 = (nr0 - m4) * r4 * smg[0] + smb[0];
            float no1 = (nr1 - m4) * r4 * smg[1] + smb[1];
            float no2 = (nr2 - m4) * r4 * smg[2] + smb[2];
            float no3 = (nr3 - m4) * r4 * smg[3] + smb[3];
            int pred = 0; float best = no0;
            if (no1 > best) { best = no1; pred = 1; }
            if (no2 > best) { best = no2; pred = 2; }
            if (no3 > best) { best = no3; pred = 3; }
            int c = label[n];
            float e0d = (c == 0) ? dt0 : (c == 1) ? dt2 : (c == 2) ? dt4 : dt6;
            float e1d = (c == 0) ? dt1 : (c == 1) ? dt3 : (c == 2) ? dt5 : dt7;
            float e0 = expf(e0d * 20.0f);   // /SK_EPS
            float e1 = expf(e1d * 20.0f);

            if (lane == 0) {
                g_e[n] = make_float2(e0, e1);
                g_code[n] = (unsigned char)(c | ((pred == c) << 2));
                // per-pixel LN scalars for k_accum: y*inv = g*(a*x + b) + be*inv
                float a_s = rstd * inv;
                g_ln[n] = make_float4(a_s, -mu * a_s, inv, 0.f);
                stage[0][w * 4 + p] = no0;
                stage[1][w * 4 + p] = no1;
                stage[2][w * 4 + p] = no2;
                stage[3][w * 4 + p] = no3;
            }
        }
        __syncthreads();
        // nearest_img[b,k,h,w]: 32-pixel chunks never cross b (32 | 12544)
        if (tid < 128) {
            int k = tid >> 5, i = tid & 31;
            int base = chunk * 32;
            int b = base / IMG;
            int off = base - b * IMG + i;
            out[(size_t)b * 4 * IMG + (size_t)k * IMG + off] = stage[k][i];
        }
        __syncthreads();
    }
}

// ---------------- K_sink: all 3 sinkhorn reductions in one persistent kernel ----------------
// grid MUST be SINK_GRID blocks (all co-resident: 296 << 1184 capacity).
__global__ void __launch_bounds__(256) k_sink() {
    __shared__ float sred[8];
    __shared__ float sw[8];
    int tid = threadIdx.x;
    const int STRIDE = SINK_GRID * 256;   // 75776

    // load per-thread pixel data ONCE into registers (<= 6 pixels/thread)
    float ex[6], ey[6];
    int cc[6];
    int base = blockIdx.x * 256 + tid;
#pragma unroll
    for (int it = 0; it < 6; it++) {
        int n = base + it * STRIDE;
        if (n < NPIX) {
            float2 e = g_e[n];
            ex[it] = e.x; ey[it] = e.y;
            cc[it] = g_code[n] & 3;
        } else cc[it] = -1;
    }

#pragma unroll 1
    for (int st = 0; st < 3; st++) {
        if (tid < 8) {
            sred[tid] = 0.f;
            if (st == 1) sw[tid] = (float)(1.0 / fmax(__ldcg(&g_E[tid]), 1e-300));
            if (st == 2) sw[tid] = (float)(1.0 / fmax(__ldcg(&g_T2[tid]), 1e-300));
        }
        __syncthreads();

        float f0 = 0.f, f1 = 0.f, f2 = 0.f, f3 = 0.f, f4 = 0.f, f5 = 0.f, f6 = 0.f, f7 = 0.f;
#pragma unroll
        for (int it = 0; it < 6; it++) {
            int c = cc[it];
            if (c < 0) continue;
            float v0, v1;
            if (st == 0) {
                v0 = ex[it]; v1 = ey[it];
            } else {
                float den = ex[it] * sw[2 * c] + ey[it] * sw[2 * c + 1];
                float ib = 1.0f / den;
                v0 = ex[it] * ib; v1 = ey[it] * ib;
            }
            switch (c) {
                case 0:  f0 += v0; f1 += v1; break;
                case 1:  f2 += v0; f3 += v1; break;
                case 2:  f4 += v0; f5 += v1; break;
                default: f6 += v0; f7 += v1; break;
            }
        }
        f0 = wsum(f0); f1 = wsum(f1); f2 = wsum(f2); f3 = wsum(f3);
        f4 = wsum(f4); f5 = wsum(f5); f6 = wsum(f6); f7 = wsum(f7);
        if ((tid & 31) == 0) {
            atomicAdd(&sred[0], f0); atomicAdd(&sred[1], f1);
            atomicAdd(&sred[2], f2); atomicAdd(&sred[3], f3);
            atomicAdd(&sred[4], f4); atomicAdd(&sred[5], f5);
            atomicAdd(&sred[6], f6); atomicAdd(&sred[7], f7);
        }
        __syncthreads();
        if (tid < 8) {
            double* dst = (st == 0) ? g_E : (st == 1) ? g_T2 : g_T3;
            atomicAdd(&dst[tid], (double)sred[tid]);
        }
        __syncthreads();

        // grid barrier between stages (not after the last)
        if (st < 2) {
            if (tid == 0) {
                __threadfence();
                atomicAdd(&g_bar[st], 1);
                while (((volatile int*)g_bar)[st] < SINK_GRID) {}
            }
            __syncthreads();
        }
    }
}

// ---------------- K_accum: target + masked feature sums (k_target merged) ----------------
__global__ void __launch_bounds__(256) k_accum(
    const float* __restrict__ feat_in,
    const float* __restrict__ fg, const float* __restrict__ fb,
    float* __restrict__ target)
{
    __shared__ float sfacc[8][DIM];
    __shared__ int   scnt[8];
    __shared__ float sw[8];
    __shared__ unsigned char sridx[8][2][32];
    int tid = threadIdx.x;
    for (int t = tid; t < 8 * DIM; t += 256) ((float*)sfacc)[t] = 0.f;
    if (tid < 8) {
        scnt[tid] = 0;
        sw[tid] = (float)(1.0 / fmax(g_T3[tid], 1e-300));
    }

    int w = tid >> 5, lane = tid & 31;
    const ulonglong2* fgp = (const ulonglong2*)fg;
    const ulonglong2* fbp = (const ulonglong2*)fb;
    ulonglong2 gA = fgp[lane], gB = fgp[lane + 32];
    ulonglong2 bA = fbp[lane], bB = fbp[lane + 32];
    u64 g2[4]  = {gA.x, gA.y, gB.x, gB.y};
    u64 be2[4] = {bA.x, bA.y, bB.x, bB.y};
    __syncthreads();

    int gw = blockIdx.x * 8 + w;             // grid=1184 -> gw in [0, 9472)
    const int WSTRIDE = 1184 * 8;            // 9472

    // ---- phase 1: target + ridx cache (each lane handles its own pixel) ----
#pragma unroll
    for (int it = 0; it < 2; it++) {
        int chunk = gw + WSTRIDE * it;
        if (chunk < NCHUNK) {
            int n = chunk * 32 + lane;
            unsigned char code = g_code[n];
            int c = code & 3;
            float2 e = g_e[n];
            int idx = (e.y * sw[2 * c + 1] > e.x * sw[2 * c]) ? 1 : 0;  // ties -> 0
            target[n] = (float)(idx + 2 * c);
            sridx[w][it][lane] = (code & 4) ? (unsigned char)(c * 2 + idx) : (unsigned char)255;
        }
    }
    // each lane wrote and reads only its own byte -> no sync needed

    // ---- phase 2: bucket-outermost accumulation ----
#pragma unroll 1
    for (int r = 0; r < 8; r++) {
        u64 acc2[4] = {0ull, 0ull, 0ull, 0ull};   // packed Σ a_n*x_nd
        float sb = 0.f, sinv = 0.f;
        int cnt = 0;
#pragma unroll
        for (int it = 0; it < 2; it++) {
            int chunk = gw + WSTRIDE * it;
            if (chunk < NCHUNK) {
                int n0 = chunk * 32;
                int rl = sridx[w][it][lane];
                unsigned mask = __ballot_sync(FULLW, rl == r);
                while (mask) {
                    int j = __ffs(mask) - 1;
                    mask &= mask - 1;
                    int n = n0 + j;

                    float4 ln = g_ln[n];             // broadcast load
                    const ulonglong2* row = (const ulonglong2*)(feat_in + (size_t)n * DIM);
                    ulonglong2 ra = row[lane], rb = row[lane + 32];
                    u64 A2 = f2_bcast(ln.x);
                    acc2[0] = f2_fma(ra.x, A2, acc2[0]);
                    acc2[1] = f2_fma(ra.y, A2, acc2[1]);
                    acc2[2] = f2_fma(rb.x, A2, acc2[2]);
                    acc2[3] = f2_fma(rb.y, A2, acc2[3]);
                    sb += ln.y; sinv += ln.z; cnt++;
                }
            }
        }
        // flush bucket r: val = g*(acc + sb) + be*sinv   (packed)
        u64 SB2 = f2_bcast(sb), SI2 = f2_bcast(sinv);
#pragma unroll
        for (int i = 0; i < 4; i++) {
            u64 t = f2_add(acc2[i], SB2);
            t = f2_mul(t, g2[i]);
            t = f2_fma(be2[i], SI2, t);
            float lo, hi; f2_unpack(t, lo, hi);
            int base = (i < 2) ? (4 * lane + 2 * i) : (128 + 4 * lane + 2 * (i - 2));
            atomicAdd(&sfacc[r][base], lo);
            atomicAdd(&sfacc[r][base + 1], hi);
        }
        if (lane == 0) atomicAdd(&scnt[r], cnt);
    }
    __syncthreads();
    for (int t = tid; t < 8 * DIM; t += 256) atomicAdd(&((float*)g_facc)[t], ((float*)sfacc)[t]);
    if (tid < 8) atomicAdd(&g_cnt[tid], scnt[tid]);
}

// ---------------- K_final: EMA update + renormalize prototypes ----------------
__global__ void k_final(float* __restrict__ out) {
    int tid = threadIdx.x;
    int r = tid >> 5, lane = tid & 31;
    float f[8]; float ss = 0.f;
#pragma unroll
    for (int i = 0; i < 8; i++) { f[i] = g_facc[r][lane + 32 * i]; ss += f[i] * f[i]; }
    ss = wsum(ss);
    float inv = 1.f / fmaxf(sqrtf(ss), 1e-12f);
    int c = r >> 1;
    bool cond = ((g_cnt[c * 2] + g_cnt[c * 2 + 1]) > 0) && (g_cnt[r] != 0);
    float u[8]; float ss2 = 0.f;
#pragma unroll
    for (int i = 0; i < 8; i++) {
        float p = g_protos[r][lane + 32 * i];
        u[i] = cond ? (0.999f * p + 0.001f * (f[i] * inv)) : p;
        ss2 += u[i] * u[i];
    }
    ss2 = wsum(ss2);
    float inv2 = 1.f / fmaxf(sqrtf(ss2), 1e-12f);
    float* np = out + OUT_PROTOS;
#pragma unroll
    for (int i = 0; i < 8; i++) np[r * DIM + lane + 32 * i] = u[i] * inv2;
}

// ---------------- launch ----------------
extern "C" void kernel_launch(void* const* d_in, const int* in_sizes, int n_in,
                              void* d_out, int out_size)
{
    const float* feat   = (const float*)d_in[0];
    const int*   label  = (const int*)  d_in[1];
    const float* protos = (const float*)d_in[2];
    const float* fg     = (const float*)d_in[3];
    const float* fb     = (const float*)d_in[4];
    const float* mg     = (const float*)d_in[5];
    const float* mb     = (const float*)d_in[6];
    float* out = (float*)d_out;

    k_init<<<1, 256>>>(protos);
    k_main<<<1184, 256>>>(feat, label, fg, fb, mg, mb, out);
    k_sink<<<SINK_GRID, 256>>>();
    k_accum<<<1184, 256>>>(feat, fg, fb, out + OUT_TARGET);
    k_final<<<1, 256>>>(out);
}